// round 1
// baseline (speedup 1.0000x reference)
#include <cuda_runtime.h>
#include <math.h>

// Problem constants (fixed shapes from reference setup_inputs)
#define BH    32            // b*h = 4*8
#define NSEQ  4096
#define DDIM  64
#define MFEAT 266
#define MPAD  272           // projT row stride (floats)
#define QPS   273           // qp_s row stride (floats) -- odd to avoid bank conflicts
#define CTXS  68            // ctx_s row stride (floats)

#define DNORM   0.35355339059327373f      // 64^-0.25
#define RATIO_C 0.061313933948496576f     // 266^-0.5
#define REPS_C  6.1313933948496576e-06f   // RATIO * 1e-4

// Scratch: static device globals (no cudaMalloc allowed)
__device__ float        g_kdd[(size_t)BH * NSEQ * MFEAT];  // stores (dd - diag) for k, ~139MB
__device__ float        g_ksum[BH * MFEAT];
__device__ float        g_ctx[BH * MFEAT * DDIM];
__device__ unsigned int g_kmax_enc;

// float <-> ordered-uint encoding for atomicMax over signed floats
__device__ __forceinline__ unsigned int enc_f(float f) {
    unsigned int u = __float_as_uint(f);
    return (u & 0x80000000u) ? ~u : (u | 0x80000000u);
}
__device__ __forceinline__ float dec_f(unsigned int k) {
    return (k & 0x80000000u) ? __uint_as_float(k & 0x7fffffffu) : __uint_as_float(~k);
}

// ---------------------------------------------------------------------------
// Kernel 0: zero accumulators, reset global max
// ---------------------------------------------------------------------------
__global__ void init_kernel() {
    int i = blockIdx.x * blockDim.x + threadIdx.x;
    int stride = gridDim.x * blockDim.x;
    if (i == 0) g_kmax_enc = 0u;   // 0 < encoding of any finite float
    for (int idx = i; idx < BH * MFEAT * DDIM; idx += stride) g_ctx[idx] = 0.f;
    for (int idx = i; idx < BH * MFEAT; idx += stride) g_ksum[idx] = 0.f;
}

// ---------------------------------------------------------------------------
// Kernel A: k data_dash GEMM. Stores (dd - diag) to g_kdd, atomicMax of dd.
// grid (NSEQ/64, BH), block 256, dynamic smem
// ---------------------------------------------------------------------------
__global__ void __launch_bounds__(256) phi_k_kernel(const float* __restrict__ k_in,
                                                    const float* __restrict__ proj) {
    extern __shared__ float sm[];
    float* projT  = sm;                       // [64][MPAD]
    float* kt     = sm + DDIM * MPAD;         // [64][65]
    float* diag_s = kt + 64 * 65;             // [64]
    float* wmax   = diag_s + 64;              // [8]

    int bh   = blockIdx.y;
    int row0 = blockIdx.x * 64;
    int tid  = threadIdx.x;

    const float* kbase = k_in + ((size_t)bh * NSEQ + row0) * DDIM;

    for (int idx = tid; idx < 64 * DDIM; idx += 256) {
        int r = idx >> 6, c = idx & 63;
        kt[r * 65 + c] = kbase[idx];
    }
    for (int idx = tid; idx < MFEAT * DDIM; idx += 256) {
        int m = idx >> 6, c = idx & 63;
        projT[c * MPAD + m] = proj[idx];
    }
    __syncthreads();

    if (tid < 64) {
        float s = 0.f;
        #pragma unroll
        for (int c = 0; c < DDIM; c++) { float x = kt[tid * 65 + c]; s += x * x; }
        diag_s[tid] = 0.0625f * s;            // 0.5 * d^-0.5
    }
    __syncthreads();

    int w = tid >> 5, l = tid & 31;
    int mi[9];
    #pragma unroll
    for (int j = 0; j < 9; j++) { int m = l + 32 * j; mi[j] = (m < MFEAT) ? m : (MFEAT - 1); }
    bool j8ok = (l < MFEAT - 256);

    float acc[8][9];
    #pragma unroll
    for (int r = 0; r < 8; r++)
        #pragma unroll
        for (int j = 0; j < 9; j++) acc[r][j] = 0.f;

    const float* ktw = kt + (8 * w) * 65;
    #pragma unroll 4
    for (int c = 0; c < DDIM; c++) {
        float pv[9];
        #pragma unroll
        for (int j = 0; j < 9; j++) pv[j] = projT[c * MPAD + mi[j]];
        #pragma unroll
        for (int r = 0; r < 8; r++) {
            float a = ktw[r * 65 + c];
            #pragma unroll
            for (int j = 0; j < 9; j++) acc[r][j] += a * pv[j];
        }
    }

    float bm = -3.0e38f;
    #pragma unroll
    for (int r = 0; r < 8; r++) {
        float dia = diag_s[8 * w + r];
        float* orow = g_kdd + ((size_t)bh * NSEQ + row0 + 8 * w + r) * MFEAT;
        #pragma unroll
        for (int j = 0; j < 8; j++) {
            float dd = DNORM * acc[r][j];
            bm = fmaxf(bm, dd);
            orow[l + 32 * j] = dd - dia;
        }
        float dd8 = DNORM * acc[r][8];
        bm = fmaxf(bm, dd8);                  // clamp duplicate: harmless for max
        if (j8ok) orow[l + 256] = dd8 - dia;
    }
    #pragma unroll
    for (int off = 16; off; off >>= 1) bm = fmaxf(bm, __shfl_xor_sync(0xffffffffu, bm, off));
    if (l == 0) wmax[w] = bm;
    __syncthreads();
    if (tid == 0) {
        float m = wmax[0];
        #pragma unroll
        for (int i = 1; i < 8; i++) m = fmaxf(m, wmax[i]);
        atomicMax(&g_kmax_enc, enc_f(m));
    }
}

// ---------------------------------------------------------------------------
// Kernel B: kp = ratio*(exp(kdd - gmax) + eps); accumulate ksum and ctx.
// grid (16, BH), block 288 (thread t owns feature m=t, t<266)
// ---------------------------------------------------------------------------
__global__ void __launch_bounds__(288) ctx_kernel(const float* __restrict__ v_in) {
    __shared__ float vsm[16 * 64];
    int bh   = blockIdx.y;
    int row0 = blockIdx.x * 256;
    int t    = threadIdx.x;

    float gmax = dec_f(g_kmax_enc);
    bool active = (t < MFEAT);

    float acc[64];
    #pragma unroll
    for (int e = 0; e < 64; e++) acc[e] = 0.f;
    float ks = 0.f;

    const float* ddb = g_kdd + ((size_t)bh * NSEQ + row0) * MFEAT + t;
    const float* vb  = v_in + ((size_t)bh * NSEQ + row0) * DDIM;

    for (int g0 = 0; g0 < 256; g0 += 16) {
        __syncthreads();
        for (int idx = t; idx < 16 * 64; idx += 288) vsm[idx] = vb[g0 * 64 + idx];
        __syncthreads();
        if (active) {
            #pragma unroll 1
            for (int r = 0; r < 16; r++) {
                float s  = ddb[(size_t)(g0 + r) * MFEAT];
                float kp = RATIO_C * __expf(s - gmax) + REPS_C;
                ks += kp;
                const float4* vr = (const float4*)(vsm + r * 64);
                #pragma unroll
                for (int e4 = 0; e4 < 16; e4++) {
                    float4 vv = vr[e4];
                    acc[4 * e4 + 0] += kp * vv.x;
                    acc[4 * e4 + 1] += kp * vv.y;
                    acc[4 * e4 + 2] += kp * vv.z;
                    acc[4 * e4 + 3] += kp * vv.w;
                }
            }
        }
    }
    if (active) {
        atomicAdd(g_ksum + bh * MFEAT + t, ks);
        float* cb = g_ctx + ((size_t)bh * MFEAT + t) * DDIM;
        #pragma unroll
        for (int e = 0; e < 64; e++) atomicAdd(cb + e, acc[e]);
    }
}

// ---------------------------------------------------------------------------
// Kernel C: fused q side: q_dd GEMM -> rowmax -> qp -> D -> out = D*(qp@ctx)
// grid (NSEQ/64, BH), block 256, dynamic smem
// ---------------------------------------------------------------------------
__global__ void __launch_bounds__(256) out_kernel(const float* __restrict__ q_in,
                                                  const float* __restrict__ proj,
                                                  float* __restrict__ out) {
    extern __shared__ float sm[];
    float* projT  = sm;                        // [64][MPAD] (phase 1)
    float* qp_s   = sm;                        // [64][QPS]  (phase 2, overlays projT)
    float* qt     = sm + 64 * QPS;             // [64][65]
    float* ctx_s  = qt + 64 * 65;              // [266][CTXS]
    float* kmean  = ctx_s + MFEAT * CTXS;      // [266]
    float* diag_s = kmean + MFEAT;             // [64]
    float* D_s    = diag_s + 64;               // [64]

    int bh   = blockIdx.y;
    int row0 = blockIdx.x * 64;
    int tid  = threadIdx.x;

    const float* qbase = q_in + ((size_t)bh * NSEQ + row0) * DDIM;

    for (int idx = tid; idx < 64 * DDIM; idx += 256) {
        int r = idx >> 6, c = idx & 63;
        qt[r * 65 + c] = qbase[idx];
    }
    for (int idx = tid; idx < MFEAT * DDIM; idx += 256) {
        int m = idx >> 6, c = idx & 63;
        projT[c * MPAD + m] = proj[idx];
    }
    for (int idx = tid; idx < MFEAT * DDIM; idx += 256)
        ctx_s[(idx >> 6) * CTXS + (idx & 63)] = g_ctx[(size_t)bh * MFEAT * DDIM + idx];
    for (int idx = tid; idx < MFEAT; idx += 256) kmean[idx] = g_ksum[bh * MFEAT + idx];
    __syncthreads();

    if (tid < 64) {
        float s = 0.f;
        #pragma unroll
        for (int c = 0; c < DDIM; c++) { float x = qt[tid * 65 + c]; s += x * x; }
        diag_s[tid] = 0.0625f * s;
    }
    __syncthreads();

    int w = tid >> 5, l = tid & 31;
    int mi[9];
    #pragma unroll
    for (int j = 0; j < 9; j++) { int m = l + 32 * j; mi[j] = (m < MFEAT) ? m : (MFEAT - 1); }
    bool j8ok = (l < MFEAT - 256);

    float acc[8][9];
    #pragma unroll
    for (int r = 0; r < 8; r++)
        #pragma unroll
        for (int j = 0; j < 9; j++) acc[r][j] = 0.f;

    const float* qtw = qt + (8 * w) * 65;
    #pragma unroll 4
    for (int c = 0; c < DDIM; c++) {
        float pv[9];
        #pragma unroll
        for (int j = 0; j < 9; j++) pv[j] = projT[c * MPAD + mi[j]];
        #pragma unroll
        for (int r = 0; r < 8; r++) {
            float a = qtw[r * 65 + c];
            #pragma unroll
            for (int j = 0; j < 9; j++) acc[r][j] += a * pv[j];
        }
    }

    // per-row: scale, rowmax, qp = ratio*(exp(dd - diag - rmax)+eps), D = 1/(qp . ksum)
    #pragma unroll
    for (int r = 0; r < 8; r++) {
        float rm = -3.0e38f;
        #pragma unroll
        for (int j = 0; j < 9; j++) { acc[r][j] *= DNORM; rm = fmaxf(rm, acc[r][j]); }
        #pragma unroll
        for (int off = 16; off; off >>= 1) rm = fmaxf(rm, __shfl_xor_sync(0xffffffffu, rm, off));
        float dia = diag_s[8 * w + r];
        float dsum = 0.f;
        #pragma unroll
        for (int j = 0; j < 9; j++) {
            float qp = RATIO_C * __expf(acc[r][j] - dia - rm) + REPS_C;
            if (j == 8 && !j8ok) qp = 0.f;        // invalid duplicate slot
            acc[r][j] = qp;
            dsum += qp * kmean[mi[j]];
        }
        #pragma unroll
        for (int off = 16; off; off >>= 1) dsum += __shfl_xor_sync(0xffffffffu, dsum, off);
        if (l == 0) D_s[8 * w + r] = 1.0f / dsum;
    }
    __syncthreads();   // all warps done reading projT before overlay write

    #pragma unroll
    for (int r = 0; r < 8; r++) {
        float* qrow = qp_s + (8 * w + r) * QPS;
        #pragma unroll
        for (int j = 0; j < 8; j++) qrow[l + 32 * j] = acc[r][j];
        if (j8ok) qrow[l + 256] = acc[r][8];
    }
    __syncthreads();

    // phase 2: out[64r x 64e] = D * (qp_s[64x266] @ ctx_s[266x64])
    int tx = tid & 15, ty = tid >> 4;
    float oacc[4][4];
    #pragma unroll
    for (int i = 0; i < 4; i++)
        #pragma unroll
        for (int jj = 0; jj < 4; jj++) oacc[i][jj] = 0.f;

    const float* cp  = ctx_s + 4 * tx;
    const float* qpp = qp_s + (4 * ty) * QPS;
    #pragma unroll 2
    for (int m = 0; m < MFEAT; m++) {
        float4 b = *(const float4*)(cp + (size_t)m * CTXS);
        float a0 = qpp[m];
        float a1 = qpp[QPS + m];
        float a2 = qpp[2 * QPS + m];
        float a3 = qpp[3 * QPS + m];
        oacc[0][0] += a0 * b.x; oacc[0][1] += a0 * b.y; oacc[0][2] += a0 * b.z; oacc[0][3] += a0 * b.w;
        oacc[1][0] += a1 * b.x; oacc[1][1] += a1 * b.y; oacc[1][2] += a1 * b.z; oacc[1][3] += a1 * b.w;
        oacc[2][0] += a2 * b.x; oacc[2][1] += a2 * b.y; oacc[2][2] += a2 * b.z; oacc[2][3] += a2 * b.w;
        oacc[3][0] += a3 * b.x; oacc[3][1] += a3 * b.y; oacc[3][2] += a3 * b.z; oacc[3][3] += a3 * b.w;
    }
    #pragma unroll
    for (int i = 0; i < 4; i++) {
        int r = 4 * ty + i;
        float ds = D_s[r];
        float4 ov = make_float4(ds * oacc[i][0], ds * oacc[i][1], ds * oacc[i][2], ds * oacc[i][3]);
        *(float4*)(out + ((size_t)bh * NSEQ + row0 + r) * DDIM + 4 * tx) = ov;
    }
}

// ---------------------------------------------------------------------------
extern "C" void kernel_launch(void* const* d_in, const int* in_sizes, int n_in,
                              void* d_out, int out_size) {
    const float* q    = (const float*)d_in[0];
    const float* k    = (const float*)d_in[1];
    const float* v    = (const float*)d_in[2];
    const float* proj = (const float*)d_in[3];
    float* out = (float*)d_out;

    const int A_SMEM = (DDIM * MPAD + 64 * 65 + 64 + 8) * 4;                         // ~86.6 KB
    const int C_SMEM = (64 * QPS + 64 * 65 + MFEAT * CTXS + MFEAT + 64 + 64) * 4;    // ~160.5 KB

    cudaFuncSetAttribute(phi_k_kernel, cudaFuncAttributeMaxDynamicSharedMemorySize, A_SMEM);
    cudaFuncSetAttribute(out_kernel,   cudaFuncAttributeMaxDynamicSharedMemorySize, C_SMEM);

    init_kernel<<<128, 256>>>();
    phi_k_kernel<<<dim3(NSEQ / 64, BH), 256, A_SMEM>>>(k, proj);
    ctx_kernel<<<dim3(16, BH), 288>>>(v);
    out_kernel<<<dim3(NSEQ / 64, BH), 256, C_SMEM>>>(q, proj, out);
}

// round 2
// speedup vs baseline: 1.1407x; 1.1407x over previous
#include <cuda_runtime.h>
#include <math.h>

#define BH    32
#define NSEQ  4096
#define DDIM  64
#define MFEAT 266
#define MPAD  274           // projT row stride (even for 8B pairs; 274%32=18 -> 2-way on transpose)
#define CTXS  66            // ctx_s row stride in kernel C (even, 8B-aligned pairs)
#define KCH   32            // K chunk in kernel C
#define NCH   9             // 9*32 = 288 >= 266 (zero padded)

#define DNORM   0.35355339059327373f
#define RATIO_C 0.061313933948496576f
#define REPS_C  6.1313933948496576e-06f

typedef unsigned long long ull;

__device__ float        g_qp [(size_t)BH * NSEQ * MFEAT];
__device__ float        g_kdd[(size_t)BH * NSEQ * MFEAT];
__device__ float        g_ksum[BH * MFEAT];
__device__ float        g_ctx[BH * MFEAT * DDIM];
__device__ unsigned int g_kmax_enc;

__device__ __forceinline__ unsigned int enc_f(float f) {
    unsigned int u = __float_as_uint(f);
    return (u & 0x80000000u) ? ~u : (u | 0x80000000u);
}
__device__ __forceinline__ float dec_f(unsigned int k) {
    return (k & 0x80000000u) ? __uint_as_float(k & 0x7fffffffu) : __uint_as_float(~k);
}

// ---- packed f32x2 helpers -------------------------------------------------
__device__ __forceinline__ ull pack2(float x, float y) {
    ull r; asm("mov.b64 %0, {%1, %2};" : "=l"(r) : "f"(x), "f"(y)); return r;
}
__device__ __forceinline__ ull dup2(float x) {
    ull r; asm("mov.b64 %0, {%1, %1};" : "=l"(r) : "f"(x)); return r;
}
__device__ __forceinline__ void unpack2(ull p, float& x, float& y) {
    asm("mov.b64 {%0, %1}, %2;" : "=f"(x), "=f"(y) : "l"(p));
}
__device__ __forceinline__ ull ffma2(ull a, ull b, ull c) {
    ull d; asm("fma.rn.f32x2 %0, %1, %2, %3;" : "=l"(d) : "l"(a), "l"(b), "l"(c)); return d;
}

// ---------------------------------------------------------------------------
__global__ void init_kernel() {
    int i = blockIdx.x * blockDim.x + threadIdx.x;
    int stride = gridDim.x * blockDim.x;
    if (i == 0) g_kmax_enc = 0u;
    for (int idx = i; idx < BH * MFEAT * DDIM; idx += stride) g_ctx[idx] = 0.f;
    for (int idx = i; idx < BH * MFEAT; idx += stride) g_ksum[idx] = 0.f;
}

// ---------------------------------------------------------------------------
// Shared GEMM macro body: dd[64 x 266] = DN * X[64x64] @ P^T. Per warp: 8 rows,
// lane owns m-pairs m = 64j + 2l (j<4 always valid; j==4 valid only l<5).
// ---------------------------------------------------------------------------
#define PHI_PROLOGUE(INPTR)                                                     \
    extern __shared__ float sm[];                                               \
    float* projT  = sm;                       /* [64][MPAD] */                  \
    float* xt     = sm + DDIM * MPAD;         /* [64][65]   */                  \
    float* diag_s = xt + 64 * 65;             /* [64]       */                  \
    float* wmax   = diag_s + 64;              /* [8]        */                  \
    int bh   = blockIdx.y;                                                      \
    int row0 = blockIdx.x * 64;                                                 \
    int tid  = threadIdx.x;                                                     \
    const float* xbase = (INPTR) + ((size_t)bh * NSEQ + row0) * DDIM;           \
    for (int idx = tid; idx < 64 * DDIM; idx += 256) {                          \
        int r = idx >> 6, c = idx & 63;                                         \
        xt[r * 65 + c] = xbase[idx];                                            \
    }                                                                           \
    for (int idx = tid; idx < MFEAT * DDIM; idx += 256) {                       \
        int m = idx >> 6, c = idx & 63;                                         \
        projT[c * MPAD + m] = proj[idx];                                        \
    }                                                                           \
    __syncthreads();                                                            \
    if (tid < 64) {                                                             \
        float s = 0.f;                                                          \
        _Pragma("unroll")                                                       \
        for (int c = 0; c < DDIM; c++) { float x = xt[tid * 65 + c]; s += x * x; } \
        diag_s[tid] = 0.0625f * s;                                              \
    }                                                                           \
    __syncthreads();                                                            \
    int w = tid >> 5, l = tid & 31;                                             \
    bool j4ok = (l < 5);                                                        \
    int m4 = 256 + 2 * (j4ok ? l : 4);    /* clamped pair index for j==4 */     \
    ull acc2[8][5];                                                             \
    _Pragma("unroll")                                                           \
    for (int r = 0; r < 8; r++)                                                 \
        _Pragma("unroll")                                                       \
        for (int j = 0; j < 5; j++) acc2[r][j] = 0ull;                          \
    const float* xtw = xt + (8 * w) * 65;                                       \
    _Pragma("unroll 4")                                                         \
    for (int c = 0; c < DDIM; c++) {                                            \
        const float* prow = projT + c * MPAD;                                   \
        ull pv[5];                                                              \
        _Pragma("unroll")                                                       \
        for (int j = 0; j < 4; j++) pv[j] = *(const ull*)(prow + 64 * j + 2 * l); \
        pv[4] = *(const ull*)(prow + m4);                                       \
        _Pragma("unroll")                                                       \
        for (int r = 0; r < 8; r++) {                                           \
            ull a2 = dup2(xtw[r * 65 + c]);                                     \
            _Pragma("unroll")                                                   \
            for (int j = 0; j < 5; j++) acc2[r][j] = ffma2(a2, pv[j], acc2[r][j]); \
        }                                                                       \
    }

// ---------------------------------------------------------------------------
// Kernel A-q: qp = ratio*(exp(DN*X@P^T - diag - rowmax) + eps) -> g_qp
// ---------------------------------------------------------------------------
__global__ void __launch_bounds__(256, 2) phi_q_kernel(const float* __restrict__ q_in,
                                                       const float* __restrict__ proj) {
    PHI_PROLOGUE(q_in)
    (void)wmax;
    #pragma unroll
    for (int r = 0; r < 8; r++) {
        float v[10];
        #pragma unroll
        for (int j = 0; j < 5; j++) unpack2(acc2[r][j], v[2 * j], v[2 * j + 1]);
        #pragma unroll
        for (int t = 0; t < 10; t++) v[t] *= DNORM;
        float rm = -3.0e38f;
        #pragma unroll
        for (int t = 0; t < 8; t++) rm = fmaxf(rm, v[t]);
        if (j4ok) rm = fmaxf(rm, fmaxf(v[8], v[9]));
        #pragma unroll
        for (int off = 16; off; off >>= 1) rm = fmaxf(rm, __shfl_xor_sync(0xffffffffu, rm, off));
        float dia = diag_s[8 * w + r] + rm;
        float* orow = g_qp + ((size_t)bh * NSEQ + row0 + 8 * w + r) * MFEAT;
        #pragma unroll
        for (int j = 0; j < 4; j++) {
            float q0 = RATIO_C * __expf(v[2 * j] - dia) + REPS_C;
            float q1 = RATIO_C * __expf(v[2 * j + 1] - dia) + REPS_C;
            *(ull*)(orow + 64 * j + 2 * l) = pack2(q0, q1);
        }
        if (j4ok) {
            float q0 = RATIO_C * __expf(v[8] - dia) + REPS_C;
            float q1 = RATIO_C * __expf(v[9] - dia) + REPS_C;
            *(ull*)(orow + 256 + 2 * l) = pack2(q0, q1);
        }
    }
}

// ---------------------------------------------------------------------------
// Kernel A-k: store (dd - diag) -> g_kdd, atomicMax(dd) -> g_kmax_enc
// ---------------------------------------------------------------------------
__global__ void __launch_bounds__(256, 2) phi_k_kernel(const float* __restrict__ k_in,
                                                       const float* __restrict__ proj) {
    PHI_PROLOGUE(k_in)
    float bm = -3.0e38f;
    #pragma unroll
    for (int r = 0; r < 8; r++) {
        float v[10];
        #pragma unroll
        for (int j = 0; j < 5; j++) unpack2(acc2[r][j], v[2 * j], v[2 * j + 1]);
        #pragma unroll
        for (int t = 0; t < 10; t++) v[t] *= DNORM;
        float dia = diag_s[8 * w + r];
        float* orow = g_kdd + ((size_t)bh * NSEQ + row0 + 8 * w + r) * MFEAT;
        #pragma unroll
        for (int t = 0; t < 8; t++) bm = fmaxf(bm, v[t]);
        #pragma unroll
        for (int j = 0; j < 4; j++)
            *(ull*)(orow + 64 * j + 2 * l) = pack2(v[2 * j] - dia, v[2 * j + 1] - dia);
        if (j4ok) {
            bm = fmaxf(bm, fmaxf(v[8], v[9]));
            *(ull*)(orow + 256 + 2 * l) = pack2(v[8] - dia, v[9] - dia);
        }
    }
    #pragma unroll
    for (int off = 16; off; off >>= 1) bm = fmaxf(bm, __shfl_xor_sync(0xffffffffu, bm, off));
    if (l == 0) wmax[w] = bm;
    __syncthreads();
    if (tid == 0) {
        float m = wmax[0];
        #pragma unroll
        for (int i = 1; i < 8; i++) m = fmaxf(m, wmax[i]);
        atomicMax(&g_kmax_enc, enc_f(m));
    }
}

// ---------------------------------------------------------------------------
// Kernel B: kp = ratio*exp(kdd - gmax)+eps; accumulate ksum and ctx (f32x2)
// grid (16, BH), block 288
// ---------------------------------------------------------------------------
__global__ void __launch_bounds__(288) ctx_kernel(const float* __restrict__ v_in) {
    __shared__ float vsm[16 * 64];
    int bh   = blockIdx.y;
    int row0 = blockIdx.x * 256;
    int t    = threadIdx.x;

    float gmax = dec_f(g_kmax_enc);
    bool active = (t < MFEAT);

    ull acc2[32];
    #pragma unroll
    for (int e = 0; e < 32; e++) acc2[e] = 0ull;
    float ks = 0.f;

    const float* ddb = g_kdd + ((size_t)bh * NSEQ + row0) * MFEAT + t;
    const float* vb  = v_in + ((size_t)bh * NSEQ + row0) * DDIM;

    for (int g0 = 0; g0 < 256; g0 += 16) {
        __syncthreads();
        for (int idx = t; idx < 16 * 64; idx += 288) vsm[idx] = vb[g0 * 64 + idx];
        __syncthreads();
        if (active) {
            #pragma unroll 1
            for (int r = 0; r < 16; r++) {
                float s  = ddb[(size_t)(g0 + r) * MFEAT];
                float kp = RATIO_C * __expf(s - gmax) + REPS_C;
                ks += kp;
                ull kp2 = dup2(kp);
                const ull* vr = (const ull*)(vsm + r * 64);
                #pragma unroll
                for (int e = 0; e < 32; e++) acc2[e] = ffma2(kp2, vr[e], acc2[e]);
            }
        }
    }
    if (active) {
        atomicAdd(g_ksum + bh * MFEAT + t, ks);
        float* cb = g_ctx + ((size_t)bh * MFEAT + t) * DDIM;
        #pragma unroll
        for (int e = 0; e < 32; e++) {
            float x, y; unpack2(acc2[e], x, y);
            atomicAdd(cb + 2 * e, x);
            atomicAdd(cb + 2 * e + 1, y);
        }
    }
}

// ---------------------------------------------------------------------------
// Kernel C: out[n,e] = (qp @ ctx) / (qp . ksum), tiled GEMM 128x64, K=266
// grid (NSEQ/128, BH), block 256 (8 col-threads x 32 row-threads),
// thread tile = 4 rows x 8 cols (4 f32x2 pairs)
// ---------------------------------------------------------------------------
__global__ void __launch_bounds__(256, 2) out_kernel(float* __restrict__ out) {
    extern __shared__ float sm[];
    float* ctx_s  = sm;                         // [NCH*KCH][CTXS] = [288][66]
    float* ksum_s = ctx_s + NCH * KCH * CTXS;   // [288]
    float* qp_s   = ksum_s + NCH * KCH;         // [128][33]

    int bh   = blockIdx.y;
    int row0 = blockIdx.x * 128;
    int tid  = threadIdx.x;
    int tc   = tid & 7;          // col group: e0 = 8*tc
    int tr   = tid >> 3;         // row group: rows 4*tr .. 4*tr+3
    int e0   = tc * 8;

    // stage ctx (padded to 288 rows with zeros) + ksum
    const float* gctx = g_ctx + (size_t)bh * MFEAT * DDIM;
    for (int idx = tid; idx < NCH * KCH * DDIM; idx += 256) {
        int m = idx >> 6, e = idx & 63;
        ctx_s[m * CTXS + e] = (m < MFEAT) ? gctx[m * DDIM + e] : 0.f;
    }
    for (int idx = tid; idx < NCH * KCH; idx += 256)
        ksum_s[idx] = (idx < MFEAT) ? g_ksum[bh * MFEAT + idx] : 0.f;

    ull acc2[4][4];
    #pragma unroll
    for (int i = 0; i < 4; i++)
        #pragma unroll
        for (int j = 0; j < 4; j++) acc2[i][j] = 0ull;
    float ds[4] = {0.f, 0.f, 0.f, 0.f};

    const float* qprow = g_qp + ((size_t)bh * NSEQ + row0) * MFEAT;

    for (int kc = 0; kc < NCH; kc++) {
        __syncthreads();
        // stage qp chunk [128][KCH] (zero-padded beyond MFEAT)
        for (int idx = tid; idx < 128 * KCH; idx += 256) {
            int r = idx >> 5, kk = idx & 31;
            int m = kc * KCH + kk;
            qp_s[r * 33 + kk] = (m < MFEAT) ? qprow[(size_t)r * MFEAT + m] : 0.f;
        }
        __syncthreads();

        const float* cbase = ctx_s + kc * KCH * CTXS + e0;
        const float* kbase = ksum_s + kc * KCH;
        #pragma unroll 4
        for (int kk = 0; kk < KCH; kk++) {
            const ull* brow = (const ull*)(cbase + kk * CTXS);
            float ksv = kbase[kk];
            ull b0 = brow[0], b1 = brow[1], b2 = brow[2], b3 = brow[3];
            #pragma unroll
            for (int i = 0; i < 4; i++) {
                float a = qp_s[(4 * tr + i) * 33 + kk];
                ds[i] += a * ksv;
                ull a2 = dup2(a);
                acc2[i][0] = ffma2(a2, b0, acc2[i][0]);
                acc2[i][1] = ffma2(a2, b1, acc2[i][1]);
                acc2[i][2] = ffma2(a2, b2, acc2[i][2]);
                acc2[i][3] = ffma2(a2, b3, acc2[i][3]);
            }
        }
    }

    #pragma unroll
    for (int i = 0; i < 4; i++) {
        float dinv = 1.0f / ds[i];
        int row = row0 + 4 * tr + i;
        float o[8];
        #pragma unroll
        for (int j = 0; j < 4; j++) { unpack2(acc2[i][j], o[2 * j], o[2 * j + 1]); }
        float* op = out + ((size_t)bh * NSEQ + row) * DDIM + e0;
        float4 v0 = make_float4(dinv * o[0], dinv * o[1], dinv * o[2], dinv * o[3]);
        float4 v1 = make_float4(dinv * o[4], dinv * o[5], dinv * o[6], dinv * o[7]);
        *(float4*)(op)     = v0;
        *(float4*)(op + 4) = v1;
    }
}

// ---------------------------------------------------------------------------
extern "C" void kernel_launch(void* const* d_in, const int* in_sizes, int n_in,
                              void* d_out, int out_size) {
    const float* q    = (const float*)d_in[0];
    const float* k    = (const float*)d_in[1];
    const float* v    = (const float*)d_in[2];
    const float* proj = (const float*)d_in[3];
    float* out = (float*)d_out;

    const int A_SMEM = (DDIM * MPAD + 64 * 65 + 64 + 8) * 4;
    const int C_SMEM = (NCH * KCH * CTXS + NCH * KCH + 128 * 33) * 4;

    cudaFuncSetAttribute(phi_q_kernel, cudaFuncAttributeMaxDynamicSharedMemorySize, A_SMEM);
    cudaFuncSetAttribute(phi_k_kernel, cudaFuncAttributeMaxDynamicSharedMemorySize, A_SMEM);
    cudaFuncSetAttribute(out_kernel,   cudaFuncAttributeMaxDynamicSharedMemorySize, C_SMEM);

    init_kernel<<<128, 256>>>();
    phi_k_kernel<<<dim3(NSEQ / 64, BH), 256, A_SMEM>>>(k, proj);
    ctx_kernel<<<dim3(16, BH), 288>>>(v);
    phi_q_kernel<<<dim3(NSEQ / 64, BH), 256, A_SMEM>>>(q, proj);
    out_kernel<<<dim3(NSEQ / 128, BH), 256, C_SMEM>>>(out);
}

// round 4
// speedup vs baseline: 1.2390x; 1.0862x over previous
#include <cuda_runtime.h>
#include <cuda_bf16.h>
#include <cstdint>

#define BH    32
#define NSEQ  4096
#define DDIM  64
#define MFEAT 266
#define MP    320
#define NT    32

#define DNORM   0.35355339059327373f
#define RATIO_C 0.061313933948496576f
#define REPS_C  6.1313933948496576e-06f
#define NEGINF  -3.0e38f

typedef unsigned long long ull;

// ---------------- global scratch (static; no cudaMalloc) --------------------
__device__ float        g_dd[(size_t)BH * NSEQ * MP];      // raw dd (k then q), 168MB
__device__ float        g_diag_k[BH * NSEQ];
__device__ float        g_diag_q[BH * NSEQ];
__device__ float        g_rmax[BH * NSEQ];
__device__ float        g_ctxTf[(size_t)BH * 72 * MP];     // ctx^T fp32 (+ksum row 64)
__device__ uint32_t     g_cthp[(size_t)BH * 72 * (MP / 2)];
__device__ uint32_t     g_ctlp[(size_t)BH * 72 * (MP / 2)];
__device__ unsigned int g_kmax_enc;

__device__ __forceinline__ unsigned int enc_f(float f) {
    unsigned int u = __float_as_uint(f);
    return (u & 0x80000000u) ? ~u : (u | 0x80000000u);
}
__device__ __forceinline__ float dec_f(unsigned int k) {
    return (k & 0x80000000u) ? __uint_as_float(k & 0x7fffffffu) : __uint_as_float(~k);
}
__device__ __forceinline__ ull dup2(float x) {
    ull r; asm("mov.b64 %0, {%1, %1};" : "=l"(r) : "f"(x)); return r;
}
__device__ __forceinline__ void unpack2(ull p, float& x, float& y) {
    asm("mov.b64 {%0, %1}, %2;" : "=f"(x), "=f"(y) : "l"(p));
}
__device__ __forceinline__ ull ffma2(ull a, ull b, ull c) {
    ull d; asm("fma.rn.f32x2 %0, %1, %2, %3;" : "=l"(d) : "l"(a), "l"(b), "l"(c)); return d;
}
__device__ __forceinline__ uint32_t smem_u32(const void* p) {
    uint32_t a;
    asm("{ .reg .u64 t; cvta.to.shared.u64 t, %1; cvt.u32.u64 %0, t; }" : "=r"(a) : "l"(p));
    return a;
}
__device__ __forceinline__ uint32_t packbf(float a, float b) {
    __nv_bfloat162 t = __floats2bfloat162_rn(a, b);
    return reinterpret_cast<uint32_t&>(t);
}
__device__ __forceinline__ void split2(float a, float b, uint32_t& hi, uint32_t& lo) {
    __nv_bfloat16 ha = __float2bfloat16_rn(a), hb = __float2bfloat16_rn(b);
    float ra = a - __bfloat162float(ha), rb = b - __bfloat162float(hb);
    __nv_bfloat162 H; H.x = ha; H.y = hb;
    hi = reinterpret_cast<uint32_t&>(H);
    lo = packbf(ra, rb);
}

// ---------------- mma.sync + ldmatrix helpers -------------------------------
__device__ __forceinline__ void ldsm_x4(uint32_t* r, uint32_t addr) {
    asm volatile("ldmatrix.sync.aligned.m8n8.x4.shared.b16 {%0,%1,%2,%3}, [%4];"
        : "=r"(r[0]), "=r"(r[1]), "=r"(r[2]), "=r"(r[3]) : "r"(addr));
}
__device__ __forceinline__ void ldsm_x2(uint32_t* r, uint32_t addr) {
    asm volatile("ldmatrix.sync.aligned.m8n8.x2.shared.b16 {%0,%1}, [%2];"
        : "=r"(r[0]), "=r"(r[1]) : "r"(addr));
}
__device__ __forceinline__ void mma_bf16(float* c, const uint32_t* a, const uint32_t* b) {
    asm volatile("mma.sync.aligned.m16n8k16.row.col.f32.bf16.bf16.f32 "
        "{%0,%1,%2,%3}, {%4,%5,%6,%7}, {%8,%9}, {%0,%1,%2,%3};"
        : "+f"(c[0]), "+f"(c[1]), "+f"(c[2]), "+f"(c[3])
        : "r"(a[0]), "r"(a[1]), "r"(a[2]), "r"(a[3]), "r"(b[0]), "r"(b[1]));
}

// ---------------- phi smem layout (bytes): row stride 144B (72 halves) ------
#define PS_AH   0
#define PS_AL   18432
#define PS_BH   36864
#define PS_BL   82944
#define PS_DIAG 129024
#define PS_RMA  129536
#define PS_RMB  130048
#define PS_SZ   130560

// ---------------------------------------------------------------------------
__global__ void init_kernel() {
    int i = blockIdx.x * blockDim.x + threadIdx.x;
    if (i == 0) g_kmax_enc = 0u;
    int n = BH * 72 * MP;
    for (int idx = i; idx < n; idx += gridDim.x * blockDim.x) g_ctxTf[idx] = 0.f;
}

// ---------------------------------------------------------------------------
// phi: dd[128 x 320] = (DN*X) @ proj^T via 3-term bf16-split mma.sync.
// ISQ: also compute per-row max -> g_rmax. else: global max -> g_kmax_enc.
// ---------------------------------------------------------------------------
template <bool ISQ>
__global__ void __launch_bounds__(256) phi_kernel(const float* __restrict__ x_in,
                                                  const float* __restrict__ proj) {
    extern __shared__ char smem[];
    uint32_t sb = smem_u32(smem);
    int tid = threadIdx.x, w = tid >> 5, lane = tid & 31;
    int bh = blockIdx.y, nt = blockIdx.x;
    const float* xb = x_in + ((size_t)bh * NSEQ + nt * 128) * DDIM;

    if (tid < 128) {
        float s = 0.f;
        #pragma unroll
        for (int c = 0; c < DDIM; c++) { float v = xb[tid * 64 + c]; s += v * v; }
        float dg = 0.0625f * s;
        float* gd = ISQ ? g_diag_q : g_diag_k;
        gd[bh * NSEQ + nt * 128 + tid] = dg;
    }
    for (int i = tid; i < 128 * 32; i += 256) {
        int r = i >> 5, p = i & 31;
        float2 v = *(const float2*)(xb + r * 64 + 2 * p);
        uint32_t hi, lo; split2(DNORM * v.x, DNORM * v.y, hi, lo);
        *(uint32_t*)(smem + PS_AH + r * 144 + 4 * p) = hi;
        *(uint32_t*)(smem + PS_AL + r * 144 + 4 * p) = lo;
    }
    for (int i = tid; i < MP * 32; i += 256) {
        int r = i >> 5, p = i & 31;
        float2 v = (r < MFEAT) ? *(const float2*)(proj + r * 64 + 2 * p) : make_float2(0.f, 0.f);
        uint32_t hi, lo; split2(v.x, v.y, hi, lo);
        *(uint32_t*)(smem + PS_BH + r * 144 + 4 * p) = hi;
        *(uint32_t*)(smem + PS_BL + r * 144 + 4 * p) = lo;
    }
    __syncthreads();

    int wr = w & 3, wc = w >> 2;
    int m0 = 32 * wr;

    // A fragments (held across all n-chunks)
    uint32_t ah[2][4][4], al[2][4][4];
    {
        int row = lane & 15;
        int koff = (lane >> 4) * 16;  // bytes
        #pragma unroll
        for (int mt = 0; mt < 2; mt++)
            #pragma unroll
            for (int k = 0; k < 4; k++) {
                uint32_t a = sb + PS_AH + (uint32_t)(m0 + mt * 16 + row) * 144 + k * 32 + koff;
                ldsm_x4(ah[mt][k], a);
                ldsm_x4(al[mt][k], a + (PS_AL - PS_AH));
            }
    }

    float rm[4] = {NEGINF, NEGINF, NEGINF, NEGINF};
    float kmx = NEGINF;
    size_t ddbase = ((size_t)(bh * NT + nt)) * 128 * MP;

    #pragma unroll 1
    for (int ch = 0; ch < 5; ch++) {
        int n0 = 160 * wc + 32 * ch;
        float acc[2][4][4];
        #pragma unroll
        for (int mt = 0; mt < 2; mt++)
            #pragma unroll
            for (int n = 0; n < 4; n++)
                #pragma unroll
                for (int x = 0; x < 4; x++) acc[mt][n][x] = 0.f;

        #pragma unroll
        for (int k = 0; k < 4; k++) {
            uint32_t bhf[4][2], blf[4][2];
            int brow = lane & 7;
            int bk = ((lane >> 3) & 1) * 16;
            #pragma unroll
            for (int n = 0; n < 4; n++) {
                uint32_t a = sb + PS_BH + (uint32_t)(n0 + n * 8 + brow) * 144 + k * 32 + bk;
                ldsm_x2(bhf[n], a);
                ldsm_x2(blf[n], a + (PS_BL - PS_BH));
            }
            #pragma unroll
            for (int mt = 0; mt < 2; mt++)
                #pragma unroll
                for (int n = 0; n < 4; n++) {
                    mma_bf16(acc[mt][n], ah[mt][k], bhf[n]);
                    mma_bf16(acc[mt][n], ah[mt][k], blf[n]);
                    mma_bf16(acc[mt][n], al[mt][k], bhf[n]);
                }
        }
        #pragma unroll
        for (int mt = 0; mt < 2; mt++)
            #pragma unroll
            for (int n = 0; n < 4; n++) {
                int col = n0 + n * 8 + 2 * (lane & 3);
                int r0 = m0 + mt * 16 + (lane >> 2);
                float c0 = acc[mt][n][0], c1 = acc[mt][n][1], c2 = acc[mt][n][2], c3 = acc[mt][n][3];
                bool v0 = col < MFEAT, v1 = col + 1 < MFEAT;
                if (ISQ) {
                    rm[2 * mt]     = fmaxf(rm[2 * mt],     fmaxf(v0 ? c0 : NEGINF, v1 ? c1 : NEGINF));
                    rm[2 * mt + 1] = fmaxf(rm[2 * mt + 1], fmaxf(v0 ? c2 : NEGINF, v1 ? c3 : NEGINF));
                } else {
                    kmx = fmaxf(kmx, fmaxf(v0 ? fmaxf(c0, c2) : NEGINF, v1 ? fmaxf(c1, c3) : NEGINF));
                }
                *(float2*)(g_dd + ddbase + (size_t)r0 * MP + col) = make_float2(c0, c1);
                *(float2*)(g_dd + ddbase + (size_t)(r0 + 8) * MP + col) = make_float2(c2, c3);
            }
    }

    if (ISQ) {
        #pragma unroll
        for (int i = 0; i < 4; i++) {
            rm[i] = fmaxf(rm[i], __shfl_xor_sync(0xffffffffu, rm[i], 1));
            rm[i] = fmaxf(rm[i], __shfl_xor_sync(0xffffffffu, rm[i], 2));
        }
        if ((lane & 3) == 0) {
            float* rb = (float*)(smem + (wc ? PS_RMB : PS_RMA));
            rb[m0 + (lane >> 2)]      = rm[0];
            rb[m0 + 8 + (lane >> 2)]  = rm[1];
            rb[m0 + 16 + (lane >> 2)] = rm[2];
            rb[m0 + 24 + (lane >> 2)] = rm[3];
        }
        __syncthreads();
        if (tid < 128)
            g_rmax[bh * NSEQ + nt * 128 + tid] =
                fmaxf(((float*)(smem + PS_RMA))[tid], ((float*)(smem + PS_RMB))[tid]);
    } else {
        #pragma unroll
        for (int off = 16; off; off >>= 1) kmx = fmaxf(kmx, __shfl_xor_sync(0xffffffffu, kmx, off));
        if (lane == 0) atomicMax(&g_kmax_enc, enc_f(kmx));
    }
}

// ---------------------------------------------------------------------------
// ctx: kp = ratio*exp(dd - diag - gmax) + eps; accumulate ctx^T + ksum row 64.
// grid (16, BH), block 288; thread t owns feature m=t (<266).
// ---------------------------------------------------------------------------
__global__ void __launch_bounds__(288) ctx_kernel(const float* __restrict__ v_in) {
    __shared__ float vsm[16 * 64];
    __shared__ float dsm[16];
    int bh = blockIdx.y, row0 = blockIdx.x * 256, t = threadIdx.x;
    float gmax = dec_f(g_kmax_enc);
    bool active = (t < MFEAT);

    ull acc2[32];
    #pragma unroll
    for (int e = 0; e < 32; e++) acc2[e] = 0ull;
    float ks = 0.f;

    const float* vb = v_in + ((size_t)bh * NSEQ + row0) * DDIM;
    const float* ddb = g_dd + ((size_t)bh * NSEQ + row0) * MP + t;
    const float* dgb = g_diag_k + bh * NSEQ + row0;

    for (int g0 = 0; g0 < 256; g0 += 16) {
        __syncthreads();
        for (int idx = t; idx < 16 * 64; idx += 288) vsm[idx] = vb[g0 * 64 + idx];
        if (t < 16) dsm[t] = dgb[g0 + t];
        __syncthreads();
        if (active) {
            #pragma unroll 1
            for (int rr = 0; rr < 16; rr++) {
                float kp = RATIO_C * __expf(ddb[(size_t)(g0 + rr) * MP] - dsm[rr] - gmax) + REPS_C;
                ks += kp;
                ull kp2 = dup2(kp);
                const ull* vr = (const ull*)(vsm + rr * 64);
                #pragma unroll
                for (int e = 0; e < 32; e++) acc2[e] = ffma2(kp2, vr[e], acc2[e]);
            }
        }
    }
    if (active) {
        float* cb = g_ctxTf + (size_t)bh * 72 * MP + t;
        #pragma unroll
        for (int e = 0; e < 32; e++) {
            float x, y; unpack2(acc2[e], x, y);
            atomicAdd(cb + (size_t)(2 * e) * MP, x);
            atomicAdd(cb + (size_t)(2 * e + 1) * MP, y);
        }
        atomicAdd(cb + (size_t)64 * MP, ks);
    }
}

// ---------------------------------------------------------------------------
__global__ void convert_kernel() {
    int i = blockIdx.x * blockDim.x + threadIdx.x;
    int n = BH * 72 * (MP / 2);
    if (i >= n) return;
    const float* src = g_ctxTf + (size_t)2 * i;
    uint32_t hi, lo; split2(src[0], src[1], hi, lo);
    g_cthp[i] = hi; g_ctlp[i] = lo;
}

// ---------------------------------------------------------------------------
// out: fused q-epilogue + GEMM. D[128 x 72] = qp[128 x 320] @ ctxT^T
// qp computed on the fly from dd_q (exp + bf16 split). col 64 = qp.ksum -> D^-1.
// smem: ctxT full (stride 656B), qp chunk (stride 144B), off[128].
// ---------------------------------------------------------------------------
#define OS_CTH 0
#define OS_CTL 47232
#define OS_QH  94464
#define OS_QL  112896
#define OS_OFF 131328
#define OS_SZ  131840

__global__ void __launch_bounds__(256) out_kernel(float* __restrict__ out) {
    extern __shared__ char smem[];
    uint32_t sb = smem_u32(smem);
    int tid = threadIdx.x, w = tid >> 5, lane = tid & 31;
    int bh = blockIdx.y, nt = blockIdx.x;

    if (tid < 128) {
        int idx = bh * NSEQ + nt * 128 + tid;
        ((float*)(smem + OS_OFF))[tid] = g_diag_q[idx] + g_rmax[idx];
    }
    for (int i = tid; i < 72 * 160; i += 256) {
        int e = i / 160, p = i % 160;
        *(uint32_t*)(smem + OS_CTH + e * 656 + 4 * p) = g_cthp[(bh * 72 + e) * 160 + p];
        *(uint32_t*)(smem + OS_CTL + e * 656 + 4 * p) = g_ctlp[(bh * 72 + e) * 160 + p];
    }

    float acc[9][4];
    #pragma unroll
    for (int n = 0; n < 9; n++)
        #pragma unroll
        for (int x = 0; x < 4; x++) acc[n][x] = 0.f;

    size_t ddbase = ((size_t)(bh * NT + nt)) * 128 * MP;

    #pragma unroll 1
    for (int ch = 0; ch < 5; ch++) {
        __syncthreads();
        for (int i = tid; i < 128 * 32; i += 256) {
            int r = i >> 5, p = i & 31;
            float2 v = *(const float2*)(g_dd + ddbase + (size_t)r * MP + ch * 64 + 2 * p);
            float off = ((float*)(smem + OS_OFF))[r];
            int col = ch * 64 + 2 * p;
            float q0 = (col     < MFEAT) ? RATIO_C * __expf(v.x - off) + REPS_C : 0.f;
            float q1 = (col + 1 < MFEAT) ? RATIO_C * __expf(v.y - off) + REPS_C : 0.f;
            uint32_t hi, lo; split2(q0, q1, hi, lo);
            *(uint32_t*)(smem + OS_QH + r * 144 + 4 * p) = hi;
            *(uint32_t*)(smem + OS_QL + r * 144 + 4 * p) = lo;
        }
        __syncthreads();

        uint32_t ah4[4][4], al4[4][4];
        {
            int row = 16 * w + (lane & 15);
            int koff = (lane >> 4) * 16;
            #pragma unroll
            for (int k = 0; k < 4; k++) {
                uint32_t a = sb + OS_QH + (uint32_t)row * 144 + k * 32 + koff;
                ldsm_x4(ah4[k], a);
                ldsm_x4(al4[k], a + (OS_QL - OS_QH));
            }
        }
        #pragma unroll
        for (int k = 0; k < 4; k++) {
            uint32_t bhf[9][2], blf[9][2];
            int brow = lane & 7;
            int bk = ((lane >> 3) & 1) * 16;
            #pragma unroll
            for (int n = 0; n < 9; n++) {
                uint32_t a = sb + OS_CTH + (uint32_t)(n * 8 + brow) * 656 + ch * 128 + k * 32 + bk;
                ldsm_x2(bhf[n], a);
                ldsm_x2(blf[n], a + (OS_CTL - OS_CTH));
            }
            #pragma unroll
            for (int n = 0; n < 9; n++) {
                mma_bf16(acc[n], ah4[k], bhf[n]);
                mma_bf16(acc[n], ah4[k], blf[n]);
                mma_bf16(acc[n], al4[k], bhf[n]);
            }
        }
    }

    float d0 = __shfl_sync(0xffffffffu, acc[8][0], lane & ~3);
    float d1 = __shfl_sync(0xffffffffu, acc[8][2], lane & ~3);
    float i0 = 1.0f / d0, i1 = 1.0f / d1;
    int r0 = nt * 128 + 16 * w + (lane >> 2);
    float* ob = out + (size_t)bh * NSEQ * DDIM;
    #pragma unroll
    for (int n = 0; n < 8; n++) {
        int col = 8 * n + 2 * (lane & 3);
        *(float2*)(ob + (size_t)r0 * DDIM + col) = make_float2(i0 * acc[n][0], i0 * acc[n][1]);
        *(float2*)(ob + (size_t)(r0 + 8) * DDIM + col) = make_float2(i1 * acc[n][2], i1 * acc[n][3]);
    }
}

// ---------------------------------------------------------------------------
extern "C" void kernel_launch(void* const* d_in, const int* in_sizes, int n_in,
                              void* d_out, int out_size) {
    const float* q    = (const float*)d_in[0];
    const float* k    = (const float*)d_in[1];
    const float* v    = (const float*)d_in[2];
    const float* proj = (const float*)d_in[3];
    float* out = (float*)d_out;

    cudaFuncSetAttribute(phi_kernel<true>,  cudaFuncAttributeMaxDynamicSharedMemorySize, PS_SZ);
    cudaFuncSetAttribute(phi_kernel<false>, cudaFuncAttributeMaxDynamicSharedMemorySize, PS_SZ);
    cudaFuncSetAttribute(out_kernel,        cudaFuncAttributeMaxDynamicSharedMemorySize, OS_SZ);

    init_kernel<<<256, 1024>>>();
    phi_kernel<false><<<dim3(NT, BH), 256, PS_SZ>>>(k, proj);
    ctx_kernel<<<dim3(16, BH), 288>>>(v);
    convert_kernel<<<(BH * 72 * (MP / 2) + 255) / 256, 256>>>();
    phi_kernel<true><<<dim3(NT, BH), 256, PS_SZ>>>(q, proj);
    out_kernel<<<dim3(NT, BH), 256, OS_SZ>>>(out);
}

// round 6
// speedup vs baseline: 1.3069x; 1.0548x over previous
#include <cuda_runtime.h>
#include <cuda_bf16.h>
#include <cstdint>

#define BH    32
#define NSEQ  4096
#define DDIM  64
#define MFEAT 266
#define MP    320
#define NT    32
#define KSPL  4            // ctx K-splits
#define KSEG  (NSEQ / KSPL)

#define DNORM   0.35355339059327373f
#define RATIO_C 0.061313933948496576f
#define REPS_C  6.1313933948496576e-06f
#define NEGINF  -3.0e38f

// ---------------- global scratch (static; no cudaMalloc) --------------------
__device__ float        g_dd[(size_t)BH * NSEQ * MP];      // raw dd (k then q), 168MB
__device__ float        g_diag_k[BH * NSEQ];
__device__ float        g_diag_q[BH * NSEQ];
__device__ float        g_rmax[BH * NSEQ];
__device__ float        g_ctxS[(size_t)KSPL * BH * 72 * MP];  // per-split ctx^T partials
__device__ uint32_t     g_cthp[(size_t)BH * 72 * (MP / 2)];
__device__ uint32_t     g_ctlp[(size_t)BH * 72 * (MP / 2)];
__device__ unsigned int g_kmax_enc;

__device__ __forceinline__ unsigned int enc_f(float f) {
    unsigned int u = __float_as_uint(f);
    return (u & 0x80000000u) ? ~u : (u | 0x80000000u);
}
__device__ __forceinline__ float dec_f(unsigned int k) {
    return (k & 0x80000000u) ? __uint_as_float(k & 0x7fffffffu) : __uint_as_float(~k);
}
__device__ __forceinline__ uint32_t smem_u32(const void* p) {
    uint32_t a;
    asm("{ .reg .u64 t; cvta.to.shared.u64 t, %1; cvt.u32.u64 %0, t; }" : "=r"(a) : "l"(p));
    return a;
}
__device__ __forceinline__ uint32_t packbf(float a, float b) {
    __nv_bfloat162 t = __floats2bfloat162_rn(a, b);
    return reinterpret_cast<uint32_t&>(t);
}
__device__ __forceinline__ void split2(float a, float b, uint32_t& hi, uint32_t& lo) {
    __nv_bfloat16 ha = __float2bfloat16_rn(a), hb = __float2bfloat16_rn(b);
    float ra = a - __bfloat162float(ha), rb = b - __bfloat162float(hb);
    __nv_bfloat162 H; H.x = ha; H.y = hb;
    hi = reinterpret_cast<uint32_t&>(H);
    lo = packbf(ra, rb);
}

// ---------------- mma.sync + ldmatrix helpers -------------------------------
__device__ __forceinline__ void ldsm_x4(uint32_t* r, uint32_t addr) {
    asm volatile("ldmatrix.sync.aligned.m8n8.x4.shared.b16 {%0,%1,%2,%3}, [%4];"
        : "=r"(r[0]), "=r"(r[1]), "=r"(r[2]), "=r"(r[3]) : "r"(addr));
}
__device__ __forceinline__ void ldsm_x2(uint32_t* r, uint32_t addr) {
    asm volatile("ldmatrix.sync.aligned.m8n8.x2.shared.b16 {%0,%1}, [%2];"
        : "=r"(r[0]), "=r"(r[1]) : "r"(addr));
}
__device__ __forceinline__ void ldsm_x4t(uint32_t* r, uint32_t addr) {
    asm volatile("ldmatrix.sync.aligned.m8n8.x4.trans.shared.b16 {%0,%1,%2,%3}, [%4];"
        : "=r"(r[0]), "=r"(r[1]), "=r"(r[2]), "=r"(r[3]) : "r"(addr));
}
__device__ __forceinline__ void ldsm_x2t(uint32_t* r, uint32_t addr) {
    asm volatile("ldmatrix.sync.aligned.m8n8.x2.trans.shared.b16 {%0,%1}, [%2];"
        : "=r"(r[0]), "=r"(r[1]) : "r"(addr));
}
__device__ __forceinline__ void mma_bf16(float* c, const uint32_t* a, const uint32_t* b) {
    asm volatile("mma.sync.aligned.m16n8k16.row.col.f32.bf16.bf16.f32 "
        "{%0,%1,%2,%3}, {%4,%5,%6,%7}, {%8,%9}, {%0,%1,%2,%3};"
        : "+f"(c[0]), "+f"(c[1]), "+f"(c[2]), "+f"(c[3])
        : "r"(a[0]), "r"(a[1]), "r"(a[2]), "r"(a[3]), "r"(b[0]), "r"(b[1]));
}

// ---------------- phi smem layout (bytes): row stride 144B ------------------
#define PS_AH   0
#define PS_AL   18432
#define PS_BH   36864
#define PS_BL   82944
#define PS_DIAG 129024
#define PS_RMA  129536
#define PS_RMB  130048
#define PS_SZ   130560

// ---------------------------------------------------------------------------
__global__ void init_kernel() {
    if (threadIdx.x == 0 && blockIdx.x == 0) g_kmax_enc = 0u;
}

// ---------------------------------------------------------------------------
// phi: dd[128 x 320] = (DN*X) @ proj^T via 3-term bf16-split mma.sync.
// ---------------------------------------------------------------------------
template <bool ISQ>
__global__ void __launch_bounds__(256) phi_kernel(const float* __restrict__ x_in,
                                                  const float* __restrict__ proj) {
    extern __shared__ char smem[];
    uint32_t sb = smem_u32(smem);
    int tid = threadIdx.x, w = tid >> 5, lane = tid & 31;
    int bh = blockIdx.y, nt = blockIdx.x;
    const float* xb = x_in + ((size_t)bh * NSEQ + nt * 128) * DDIM;

    if (tid < 128) {
        float s = 0.f;
        #pragma unroll
        for (int c = 0; c < DDIM; c++) { float v = xb[tid * 64 + c]; s += v * v; }
        float dg = 0.0625f * s;
        float* gd = ISQ ? g_diag_q : g_diag_k;
        gd[bh * NSEQ + nt * 128 + tid] = dg;
    }
    for (int i = tid; i < 128 * 32; i += 256) {
        int r = i >> 5, p = i & 31;
        float2 v = *(const float2*)(xb + r * 64 + 2 * p);
        uint32_t hi, lo; split2(DNORM * v.x, DNORM * v.y, hi, lo);
        *(uint32_t*)(smem + PS_AH + r * 144 + 4 * p) = hi;
        *(uint32_t*)(smem + PS_AL + r * 144 + 4 * p) = lo;
    }
    for (int i = tid; i < MP * 32; i += 256) {
        int r = i >> 5, p = i & 31;
        float2 v = (r < MFEAT) ? *(const float2*)(proj + r * 64 + 2 * p) : make_float2(0.f, 0.f);
        uint32_t hi, lo; split2(v.x, v.y, hi, lo);
        *(uint32_t*)(smem + PS_BH + r * 144 + 4 * p) = hi;
        *(uint32_t*)(smem + PS_BL + r * 144 + 4 * p) = lo;
    }
    __syncthreads();

    int wr = w & 3, wc = w >> 2;
    int m0 = 32 * wr;

    uint32_t ah[2][4][4], al[2][4][4];
    {
        int row = lane & 15;
        int koff = (lane >> 4) * 16;
        #pragma unroll
        for (int mt = 0; mt < 2; mt++)
            #pragma unroll
            for (int k = 0; k < 4; k++) {
                uint32_t a = sb + PS_AH + (uint32_t)(m0 + mt * 16 + row) * 144 + k * 32 + koff;
                ldsm_x4(ah[mt][k], a);
                ldsm_x4(al[mt][k], a + (PS_AL - PS_AH));
            }
    }

    float rm[4] = {NEGINF, NEGINF, NEGINF, NEGINF};
    float kmx = NEGINF;
    size_t ddbase = ((size_t)(bh * NT + nt)) * 128 * MP;

    #pragma unroll 1
    for (int ch = 0; ch < 5; ch++) {
        int n0 = 160 * wc + 32 * ch;
        float acc[2][4][4];
        #pragma unroll
        for (int mt = 0; mt < 2; mt++)
            #pragma unroll
            for (int n = 0; n < 4; n++)
                #pragma unroll
                for (int x = 0; x < 4; x++) acc[mt][n][x] = 0.f;

        #pragma unroll
        for (int k = 0; k < 4; k++) {
            uint32_t bhf[4][2], blf[4][2];
            int brow = lane & 7;
            int bk = ((lane >> 3) & 1) * 16;
            #pragma unroll
            for (int n = 0; n < 4; n++) {
                uint32_t a = sb + PS_BH + (uint32_t)(n0 + n * 8 + brow) * 144 + k * 32 + bk;
                ldsm_x2(bhf[n], a);
                ldsm_x2(blf[n], a + (PS_BL - PS_BH));
            }
            #pragma unroll
            for (int mt = 0; mt < 2; mt++)
                #pragma unroll
                for (int n = 0; n < 4; n++) {
                    mma_bf16(acc[mt][n], ah[mt][k], bhf[n]);
                    mma_bf16(acc[mt][n], ah[mt][k], blf[n]);
                    mma_bf16(acc[mt][n], al[mt][k], bhf[n]);
                }
        }
        #pragma unroll
        for (int mt = 0; mt < 2; mt++)
            #pragma unroll
            for (int n = 0; n < 4; n++) {
                int col = n0 + n * 8 + 2 * (lane & 3);
                int r0 = m0 + mt * 16 + (lane >> 2);
                float c0 = acc[mt][n][0], c1 = acc[mt][n][1], c2 = acc[mt][n][2], c3 = acc[mt][n][3];
                bool v0 = col < MFEAT, v1 = col + 1 < MFEAT;
                if (ISQ) {
                    rm[2 * mt]     = fmaxf(rm[2 * mt],     fmaxf(v0 ? c0 : NEGINF, v1 ? c1 : NEGINF));
                    rm[2 * mt + 1] = fmaxf(rm[2 * mt + 1], fmaxf(v0 ? c2 : NEGINF, v1 ? c3 : NEGINF));
                } else {
                    kmx = fmaxf(kmx, fmaxf(v0 ? fmaxf(c0, c2) : NEGINF, v1 ? fmaxf(c1, c3) : NEGINF));
                }
                *(float2*)(g_dd + ddbase + (size_t)r0 * MP + col) = make_float2(c0, c1);
                *(float2*)(g_dd + ddbase + (size_t)(r0 + 8) * MP + col) = make_float2(c2, c3);
            }
    }

    if (ISQ) {
        #pragma unroll
        for (int i = 0; i < 4; i++) {
            rm[i] = fmaxf(rm[i], __shfl_xor_sync(0xffffffffu, rm[i], 1));
            rm[i] = fmaxf(rm[i], __shfl_xor_sync(0xffffffffu, rm[i], 2));
        }
        if ((lane & 3) == 0) {
            float* rb = (float*)(smem + (wc ? PS_RMB : PS_RMA));
            rb[m0 + (lane >> 2)]      = rm[0];
            rb[m0 + 8 + (lane >> 2)]  = rm[1];
            rb[m0 + 16 + (lane >> 2)] = rm[2];
            rb[m0 + 24 + (lane >> 2)] = rm[3];
        }
        __syncthreads();
        if (tid < 128)
            g_rmax[bh * NSEQ + nt * 128 + tid] =
                fmaxf(((float*)(smem + PS_RMA))[tid], ((float*)(smem + PS_RMB))[tid]);
    } else {
        #pragma unroll
        for (int off = 16; off; off >>= 1) kmx = fmaxf(kmx, __shfl_xor_sync(0xffffffffu, kmx, off));
        if (lane == 0) atomicMax(&g_kmax_enc, enc_f(kmx));
    }
}

// ---------------------------------------------------------------------------
// ctx (tensorized): C[m, e] = sum_n kp[n, m] * w[n, e],  w = [v | 1 | 0...]
// grid (2*KSPL, BH), block 160 (5 warps x 32 m-rows of the 160-col m-tile).
// kp computed on the fly from dd_k (exp + bf16 split), ldmatrix.trans operands.
// Partial C (K-split) stored non-atomically to g_ctxS slab [ks][bh][e][m].
// ---------------------------------------------------------------------------
#define CA_HI 0
#define CA_LO 21504
#define CB_HI 43008
#define CB_LO 54272
#define CS_SZ 65536

__global__ void __launch_bounds__(160, 2) ctx_mma_kernel(const float* __restrict__ v_in) {
    extern __shared__ char smem[];
    uint32_t sb = smem_u32(smem);
    int tid = threadIdx.x, w = tid >> 5, lane = tid & 31;
    int bh = blockIdx.y;
    int mt = blockIdx.x & 1, ks = blockIdx.x >> 1;
    float gmax = dec_f(g_kmax_enc);

    float acc[2][9][4];
    #pragma unroll
    for (int t = 0; t < 2; t++)
        #pragma unroll
        for (int n = 0; n < 9; n++)
            #pragma unroll
            for (int x = 0; x < 4; x++) acc[t][n][x] = 0.f;

    #pragma unroll 1
    for (int c = 0; c < KSEG / 64; c++) {
        int n0 = ks * KSEG + c * 64;
        __syncthreads();
        // stage A: kp[k=64 n-rows][160 m-cols] bf16 hi/lo (stride 336B)
        for (int idx = tid; idx < 64 * 80; idx += 160) {
            int k = idx / 80, p = idx % 80;
            int n = n0 + k;
            int mg = mt * 160 + 2 * p;
            float2 dv = *(const float2*)(g_dd + ((size_t)bh * NSEQ + n) * MP + mg);
            float off = g_diag_k[bh * NSEQ + n] + gmax;
            float k0 = (mg     < MFEAT) ? RATIO_C * __expf(dv.x - off) + REPS_C : 0.f;
            float k1 = (mg + 1 < MFEAT) ? RATIO_C * __expf(dv.y - off) + REPS_C : 0.f;
            uint32_t hi, lo; split2(k0, k1, hi, lo);
            *(uint32_t*)(smem + CA_HI + k * 336 + 4 * p) = hi;
            *(uint32_t*)(smem + CA_LO + k * 336 + 4 * p) = lo;
        }
        // stage B: w[k=64][72 e-cols] bf16 hi/lo (stride 176B)
        for (int idx = tid; idx < 64 * 36; idx += 160) {
            int k = idx / 36, p = idx % 36;
            int e = 2 * p;
            float2 wv;
            if (e < 64)       wv = *(const float2*)(v_in + ((size_t)bh * NSEQ + n0 + k) * DDIM + e);
            else if (e == 64) wv = make_float2(1.f, 0.f);
            else              wv = make_float2(0.f, 0.f);
            uint32_t hi, lo; split2(wv.x, wv.y, hi, lo);
            *(uint32_t*)(smem + CB_HI + k * 176 + 4 * p) = hi;
            *(uint32_t*)(smem + CB_LO + k * 176 + 4 * p) = lo;
        }
        __syncthreads();

        #pragma unroll
        for (int kk = 0; kk < 4; kk++) {
            uint32_t ah[2][4], al[2][4];
            int kra = (lane & 7) + 8 * ((lane >> 4) & 1);
            int mh = ((lane >> 3) & 1) * 16;
            #pragma unroll
            for (int t = 0; t < 2; t++) {
                uint32_t a = sb + CA_HI + (uint32_t)(kk * 16 + kra) * 336 + 64 * w + 32 * t + mh;
                ldsm_x4t(ah[t], a);
                ldsm_x4t(al[t], a + (CA_LO - CA_HI));
            }
            uint32_t bhf[9][2], blf[9][2];
            int krb = (lane & 7) + 8 * ((lane >> 3) & 1);
            #pragma unroll
            for (int n = 0; n < 9; n++) {
                uint32_t a = sb + CB_HI + (uint32_t)(kk * 16 + krb) * 176 + 16 * n;
                ldsm_x2t(bhf[n], a);
                ldsm_x2t(blf[n], a + (CB_LO - CB_HI));
            }
            #pragma unroll
            for (int t = 0; t < 2; t++)
                #pragma unroll
                for (int n = 0; n < 9; n++) {
                    mma_bf16(acc[t][n], ah[t], bhf[n]);
                    mma_bf16(acc[t][n], ah[t], blf[n]);
                    mma_bf16(acc[t][n], al[t], bhf[n]);
                }
        }
    }

    // store partial C to slab [ks][bh][e][m]
    float* slab = g_ctxS + ((size_t)(ks * BH + bh)) * 72 * MP;
    #pragma unroll
    for (int t = 0; t < 2; t++)
        #pragma unroll
        for (int n = 0; n < 9; n++) {
            int mg = mt * 160 + 32 * w + 16 * t + (lane >> 2);
            int e = 8 * n + 2 * (lane & 3);
            slab[(size_t)e * MP + mg]           = acc[t][n][0];
            slab[(size_t)(e + 1) * MP + mg]     = acc[t][n][1];
            slab[(size_t)e * MP + mg + 8]       = acc[t][n][2];
            slab[(size_t)(e + 1) * MP + mg + 8] = acc[t][n][3];
        }
}

// ---------------------------------------------------------------------------
// convert: sum K-split slabs, split to bf16 hi/lo pairs for the out GEMM.
// ---------------------------------------------------------------------------
__global__ void convert_kernel() {
    int i = blockIdx.x * blockDim.x + threadIdx.x;
    int n = BH * 72 * (MP / 2);
    if (i >= n) return;
    int bh = i / (72 * 160), rem = i % (72 * 160);
    int e = rem / 160, p = rem % 160;
    float sx = 0.f, sy = 0.f;
    #pragma unroll
    for (int ks = 0; ks < KSPL; ks++) {
        float2 v = *(const float2*)(g_ctxS + (((size_t)(ks * BH + bh)) * 72 + e) * MP + 2 * p);
        sx += v.x; sy += v.y;
    }
    uint32_t hi, lo; split2(sx, sy, hi, lo);
    g_cthp[i] = hi; g_ctlp[i] = lo;
}

// ---------------------------------------------------------------------------
// out: fused q-epilogue + GEMM. D[128 x 72] = qp[128 x 320] @ ctxT^T
// ---------------------------------------------------------------------------
#define OS_CTH 0
#define OS_CTL 47232
#define OS_QH  94464
#define OS_QL  112896
#define OS_OFF 131328
#define OS_SZ  131840

__global__ void __launch_bounds__(256) out_kernel(float* __restrict__ out) {
    extern __shared__ char smem[];
    uint32_t sb = smem_u32(smem);
    int tid = threadIdx.x, w = tid >> 5, lane = tid & 31;
    int bh = blockIdx.y, nt = blockIdx.x;

    if (tid < 128) {
        int idx = bh * NSEQ + nt * 128 + tid;
        ((float*)(smem + OS_OFF))[tid] = g_diag_q[idx] + g_rmax[idx];
    }
    for (int i = tid; i < 72 * 160; i += 256) {
        int e = i / 160, p = i % 160;
        *(uint32_t*)(smem + OS_CTH + e * 656 + 4 * p) = g_cthp[(bh * 72 + e) * 160 + p];
        *(uint32_t*)(smem + OS_CTL + e * 656 + 4 * p) = g_ctlp[(bh * 72 + e) * 160 + p];
    }

    float acc[9][4];
    #pragma unroll
    for (int n = 0; n < 9; n++)
        #pragma unroll
        for (int x = 0; x < 4; x++) acc[n][x] = 0.f;

    size_t ddbase = ((size_t)(bh * NT + nt)) * 128 * MP;

    #pragma unroll 1
    for (int ch = 0; ch < 5; ch++) {
        __syncthreads();
        for (int i = tid; i < 128 * 32; i += 256) {
            int r = i >> 5, p = i & 31;
            float2 v = *(const float2*)(g_dd + ddbase + (size_t)r * MP + ch * 64 + 2 * p);
            float off = ((float*)(smem + OS_OFF))[r];
            int col = ch * 64 + 2 * p;
            float q0 = (col     < MFEAT) ? RATIO_C * __expf(v.x - off) + REPS_C : 0.f;
            float q1 = (col + 1 < MFEAT) ? RATIO_C * __expf(v.y - off) + REPS_C : 0.f;
            uint32_t hi, lo; split2(q0, q1, hi, lo);
            *(uint32_t*)(smem + OS_QH + r * 144 + 4 * p) = hi;
            *(uint32_t*)(smem + OS_QL + r * 144 + 4 * p) = lo;
        }
        __syncthreads();

        uint32_t ah4[4][4], al4[4][4];
        {
            int row = 16 * w + (lane & 15);
            int koff = (lane >> 4) * 16;
            #pragma unroll
            for (int k = 0; k < 4; k++) {
                uint32_t a = sb + OS_QH + (uint32_t)row * 144 + k * 32 + koff;
                ldsm_x4(ah4[k], a);
                ldsm_x4(al4[k], a + (OS_QL - OS_QH));
            }
        }
        #pragma unroll
        for (int k = 0; k < 4; k++) {
            uint32_t bhf[9][2], blf[9][2];
            int brow = lane & 7;
            int bk = ((lane >> 3) & 1) * 16;
            #pragma unroll
            for (int n = 0; n < 9; n++) {
                uint32_t a = sb + OS_CTH + (uint32_t)(n * 8 + brow) * 656 + ch * 128 + k * 32 + bk;
                ldsm_x2(bhf[n], a);
                ldsm_x2(blf[n], a + (OS_CTL - OS_CTH));
            }
            #pragma unroll
            for (int n = 0; n < 9; n++) {
                mma_bf16(acc[n], ah4[k], bhf[n]);
                mma_bf16(acc[n], ah4[k], blf[n]);
                mma_bf16(acc[n], al4[k], bhf[n]);
            }
        }
    }

    float d0 = __shfl_sync(0xffffffffu, acc[8][0], lane & ~3);
    float d1 = __shfl_sync(0xffffffffu, acc[8][2], lane & ~3);
    float i0 = 1.0f / d0, i1 = 1.0f / d1;
    int r0 = nt * 128 + 16 * w + (lane >> 2);
    float* ob = out + (size_t)bh * NSEQ * DDIM;
    #pragma unroll
    for (int n = 0; n < 8; n++) {
        int col = 8 * n + 2 * (lane & 3);
        *(float2*)(ob + (size_t)r0 * DDIM + col) = make_float2(i0 * acc[n][0], i0 * acc[n][1]);
        *(float2*)(ob + (size_t)(r0 + 8) * DDIM + col) = make_float2(i1 * acc[n][2], i1 * acc[n][3]);
    }
}

// ---------------------------------------------------------------------------
extern "C" void kernel_launch(void* const* d_in, const int* in_sizes, int n_in,
                              void* d_out, int out_size) {
    const float* q    = (const float*)d_in[0];
    const float* k    = (const float*)d_in[1];
    const float* v    = (const float*)d_in[2];
    const float* proj = (const float*)d_in[3];
    float* out = (float*)d_out;

    cudaFuncSetAttribute(phi_kernel<true>,  cudaFuncAttributeMaxDynamicSharedMemorySize, PS_SZ);
    cudaFuncSetAttribute(phi_kernel<false>, cudaFuncAttributeMaxDynamicSharedMemorySize, PS_SZ);
    cudaFuncSetAttribute(ctx_mma_kernel,    cudaFuncAttributeMaxDynamicSharedMemorySize, CS_SZ);
    cudaFuncSetAttribute(out_kernel,        cudaFuncAttributeMaxDynamicSharedMemorySize, OS_SZ);

    init_kernel<<<1, 32>>>();
    phi_kernel<false><<<dim3(NT, BH), 256, PS_SZ>>>(k, proj);
    ctx_mma_kernel<<<dim3(2 * KSPL, BH), 160, CS_SZ>>>(v);
    convert_kernel<<<(BH * 72 * (MP / 2) + 255) / 256, 256>>>();
    phi_kernel<true><<<dim3(NT, BH), 256, PS_SZ>>>(q, proj);
    out_kernel<<<dim3(NT, BH), 256, OS_SZ>>>(out);
}

// round 7
// speedup vs baseline: 1.6300x; 1.2472x over previous
#include <cuda_runtime.h>
#include <cuda_bf16.h>
#include <cstdint>

#define BH    32
#define NSEQ  4096
#define DDIM  64
#define MFEAT 266
#define MP    320
#define NT    32
#define KSPL  8
#define KSEG  (NSEQ / KSPL)

#define DNORM   0.35355339059327373f
#define RATIO_C 0.061313933948496576f
#define REPS_C  6.1313933948496576e-06f
#define NEGINF  -3.0e38f

// ---------------- global scratch (static; no cudaMalloc) --------------------
__device__ float        g_ctxS[(size_t)KSPL * BH * 72 * MP];   // K-split ctx^T partials
__device__ uint32_t     g_cthp[(size_t)BH * 72 * 160];         // ctx^T hi bf16 pairs
__device__ uint32_t     g_ctlp[(size_t)BH * 72 * 160];         // ctx^T lo bf16 pairs
__device__ unsigned int g_kmax_enc;

__device__ __forceinline__ unsigned int enc_f(float f) {
    unsigned int u = __float_as_uint(f);
    return (u & 0x80000000u) ? ~u : (u | 0x80000000u);
}
__device__ __forceinline__ float dec_f(unsigned int k) {
    return (k & 0x80000000u) ? __uint_as_float(k & 0x7fffffffu) : __uint_as_float(~k);
}
__device__ __forceinline__ uint32_t smem_u32(const void* p) {
    uint32_t a;
    asm("{ .reg .u64 t; cvta.to.shared.u64 t, %1; cvt.u32.u64 %0, t; }" : "=r"(a) : "l"(p));
    return a;
}
__device__ __forceinline__ uint32_t packbf(float a, float b) {
    __nv_bfloat162 t = __floats2bfloat162_rn(a, b);
    return reinterpret_cast<uint32_t&>(t);
}
__device__ __forceinline__ void split2(float a, float b, uint32_t& hi, uint32_t& lo) {
    __nv_bfloat16 ha = __float2bfloat16_rn(a), hb = __float2bfloat16_rn(b);
    float ra = a - __bfloat162float(ha), rb = b - __bfloat162float(hb);
    __nv_bfloat162 H; H.x = ha; H.y = hb;
    hi = reinterpret_cast<uint32_t&>(H);
    lo = packbf(ra, rb);
}

// ---------------- mma.sync + ldmatrix helpers -------------------------------
__device__ __forceinline__ void ldsm_x4(uint32_t* r, uint32_t addr) {
    asm volatile("ldmatrix.sync.aligned.m8n8.x4.shared.b16 {%0,%1,%2,%3}, [%4];"
        : "=r"(r[0]), "=r"(r[1]), "=r"(r[2]), "=r"(r[3]) : "r"(addr));
}
__device__ __forceinline__ void ldsm_x2(uint32_t* r, uint32_t addr) {
    asm volatile("ldmatrix.sync.aligned.m8n8.x2.shared.b16 {%0,%1}, [%2];"
        : "=r"(r[0]), "=r"(r[1]) : "r"(addr));
}
__device__ __forceinline__ void ldsm_x4t(uint32_t* r, uint32_t addr) {
    asm volatile("ldmatrix.sync.aligned.m8n8.x4.trans.shared.b16 {%0,%1,%2,%3}, [%4];"
        : "=r"(r[0]), "=r"(r[1]), "=r"(r[2]), "=r"(r[3]) : "r"(addr));
}
__device__ __forceinline__ void ldsm_x2t(uint32_t* r, uint32_t addr) {
    asm volatile("ldmatrix.sync.aligned.m8n8.x2.trans.shared.b16 {%0,%1}, [%2];"
        : "=r"(r[0]), "=r"(r[1]) : "r"(addr));
}
__device__ __forceinline__ void mma_bf16(float* c, const uint32_t* a, const uint32_t* b) {
    asm volatile("mma.sync.aligned.m16n8k16.row.col.f32.bf16.bf16.f32 "
        "{%0,%1,%2,%3}, {%4,%5,%6,%7}, {%8,%9}, {%0,%1,%2,%3};"
        : "+f"(c[0]), "+f"(c[1]), "+f"(c[2]), "+f"(c[3])
        : "r"(a[0]), "r"(a[1]), "r"(a[2]), "r"(a[3]), "r"(b[0]), "r"(b[1]));
}

// ---------------------------------------------------------------------------
__global__ void init_kernel() {
    if (threadIdx.x == 0 && blockIdx.x == 0) g_kmax_enc = 0u;
}

// ---------------------------------------------------------------------------
// kmax: global max of dd_k via hi-only bf16 GEMM (stabilizer; precision slack
// cancels between numerator and denominator). No dd stores.
// ---------------------------------------------------------------------------
#define KA_H 0
#define KB_H 18432
#define KM_SZ 64512

__global__ void __launch_bounds__(256) kmax_kernel(const float* __restrict__ k_in,
                                                   const float* __restrict__ proj) {
    extern __shared__ char smem[];
    uint32_t sb = smem_u32(smem);
    int tid = threadIdx.x, w = tid >> 5, lane = tid & 31;
    int bh = blockIdx.y, nt = blockIdx.x;
    const float* kb = k_in + ((size_t)bh * NSEQ + nt * 128) * DDIM;

    for (int i = tid; i < 128 * 32; i += 256) {
        int r = i >> 5, p = i & 31;
        float2 v = *(const float2*)(kb + r * 64 + 2 * p);
        *(uint32_t*)(smem + KA_H + r * 144 + 4 * p) = packbf(DNORM * v.x, DNORM * v.y);
    }
    for (int i = tid; i < MP * 32; i += 256) {
        int r = i >> 5, p = i & 31;
        float2 v = (r < MFEAT) ? *(const float2*)(proj + r * 64 + 2 * p) : make_float2(0.f, 0.f);
        *(uint32_t*)(smem + KB_H + r * 144 + 4 * p) = packbf(v.x, v.y);
    }
    __syncthreads();

    int wr = w & 3, wc = w >> 2, m0 = 32 * wr;
    float kmx = NEGINF;

    #pragma unroll 1
    for (int ch = 0; ch < 5; ch++) {
        int n0 = 160 * wc + 32 * ch;
        float acc[2][4][4];
        #pragma unroll
        for (int mt = 0; mt < 2; mt++)
            #pragma unroll
            for (int n = 0; n < 4; n++)
                #pragma unroll
                for (int x = 0; x < 4; x++) acc[mt][n][x] = 0.f;
        #pragma unroll
        for (int kt = 0; kt < 4; kt++) {
            uint32_t ah[2][4];
            int arow = lane & 15, koff = (lane >> 4) * 16;
            #pragma unroll
            for (int mt = 0; mt < 2; mt++)
                ldsm_x4(ah[mt], sb + KA_H + (uint32_t)(m0 + 16 * mt + arow) * 144 + kt * 32 + koff);
            uint32_t bf[4][2];
            int brow = lane & 7, bk = ((lane >> 3) & 1) * 16;
            #pragma unroll
            for (int n = 0; n < 4; n++)
                ldsm_x2(bf[n], sb + KB_H + (uint32_t)(n0 + 8 * n + brow) * 144 + kt * 32 + bk);
            #pragma unroll
            for (int mt = 0; mt < 2; mt++)
                #pragma unroll
                for (int n = 0; n < 4; n++) mma_bf16(acc[mt][n], ah[mt], bf[n]);
        }
        #pragma unroll
        for (int mt = 0; mt < 2; mt++)
            #pragma unroll
            for (int n = 0; n < 4; n++) {
                int col = n0 + 8 * n + 2 * (lane & 3);
                bool v0 = col < MFEAT, v1 = col + 1 < MFEAT;
                kmx = fmaxf(kmx, fmaxf(v0 ? fmaxf(acc[mt][n][0], acc[mt][n][2]) : NEGINF,
                                       v1 ? fmaxf(acc[mt][n][1], acc[mt][n][3]) : NEGINF));
            }
    }
    #pragma unroll
    for (int off = 16; off; off >>= 1) kmx = fmaxf(kmx, __shfl_xor_sync(0xffffffffu, kmx, off));
    if (lane == 0) atomicMax(&g_kmax_enc, enc_f(kmx));
}

// ---------------------------------------------------------------------------
// ctx_fused: recompute dd_k in-kernel (3-term), exp -> kp bf16 smem,
// trans-ldmatrix GEMM vs [v|1]. C partials -> K-split slabs.
// grid (2 m-halves * 8 ks, BH), block 160.
// ---------------------------------------------------------------------------
#define CP_H 0
#define CP_L 23040
#define CK_H 46080
#define CK_L 55296
#define CT_H 64512
#define CT_L 86016
#define CW_H 107520
#define CW_L 118784
#define CD_  130048
#define CX_SZ 130304

__global__ void __launch_bounds__(160) ctx_fused(const float* __restrict__ k_in,
                                                 const float* __restrict__ v_in,
                                                 const float* __restrict__ proj) {
    extern __shared__ char smem[];
    uint32_t sb = smem_u32(smem);
    int tid = threadIdx.x, w = tid >> 5, lane = tid & 31;
    int bh = blockIdx.y, mhalf = blockIdx.x & 1, ks = blockIdx.x >> 1;
    float gmax = dec_f(g_kmax_enc);

    // stage proj half [160 m rows x 64 k] hi/lo
    for (int i = tid; i < 160 * 32; i += 160) {
        int r = i >> 5, p = i & 31;
        int m = mhalf * 160 + r;
        float2 v = (m < MFEAT) ? *(const float2*)(proj + m * 64 + 2 * p) : make_float2(0.f, 0.f);
        uint32_t hi, lo; split2(v.x, v.y, hi, lo);
        *(uint32_t*)(smem + CP_H + r * 144 + 4 * p) = hi;
        *(uint32_t*)(smem + CP_L + r * 144 + 4 * p) = lo;
    }

    float accC[2][9][4];
    #pragma unroll
    for (int t = 0; t < 2; t++)
        #pragma unroll
        for (int n = 0; n < 9; n++)
            #pragma unroll
            for (int x = 0; x < 4; x++) accC[t][n][x] = 0.f;

    #pragma unroll 1
    for (int c = 0; c < KSEG / 64; c++) {
        int n0 = ks * KSEG + c * 64;
        __syncthreads();   // protect CK/CW/CT vs previous iteration reads
        const float* kb = k_in + ((size_t)bh * NSEQ + n0) * DDIM;
        for (int i = tid; i < 64 * 32; i += 160) {
            int r = i >> 5, p = i & 31;
            float2 v = *(const float2*)(kb + r * 64 + 2 * p);
            uint32_t hi, lo; split2(DNORM * v.x, DNORM * v.y, hi, lo);
            *(uint32_t*)(smem + CK_H + r * 144 + 4 * p) = hi;
            *(uint32_t*)(smem + CK_L + r * 144 + 4 * p) = lo;
        }
        const float* vb = v_in + ((size_t)bh * NSEQ + n0) * DDIM;
        for (int i = tid; i < 64 * 36; i += 160) {
            int r = i / 36, p = i % 36;
            int e = 2 * p;
            float2 wv;
            if (e < 64)       wv = *(const float2*)(vb + r * 64 + e);
            else if (e == 64) wv = make_float2(1.f, 0.f);
            else              wv = make_float2(0.f, 0.f);
            uint32_t hi, lo; split2(wv.x, wv.y, hi, lo);
            *(uint32_t*)(smem + CW_H + r * 176 + 4 * p) = hi;
            *(uint32_t*)(smem + CW_L + r * 176 + 4 * p) = lo;
        }
        if (tid < 64) {
            float s = 0.f;
            #pragma unroll
            for (int c2 = 0; c2 < DDIM; c2++) { float x = kb[tid * 64 + c2]; s += x * x; }
            ((float*)(smem + CD_))[tid] = 0.0625f * s;
        }
        __syncthreads();

        // GEMM1: dd[64 n x 160 m], warp cols 32*w
        float acc1[4][4][4];
        #pragma unroll
        for (int mt = 0; mt < 4; mt++)
            #pragma unroll
            for (int n = 0; n < 4; n++)
                #pragma unroll
                for (int x = 0; x < 4; x++) acc1[mt][n][x] = 0.f;
        int n0w = 32 * w;
        #pragma unroll
        for (int kt = 0; kt < 4; kt++) {
            uint32_t ah[4][4], al[4][4];
            int arow = lane & 15, koff = (lane >> 4) * 16;
            #pragma unroll
            for (int mt = 0; mt < 4; mt++) {
                uint32_t a = sb + CK_H + (uint32_t)(16 * mt + arow) * 144 + kt * 32 + koff;
                ldsm_x4(ah[mt], a);
                ldsm_x4(al[mt], a + (CK_L - CK_H));
            }
            uint32_t bhf[4][2], blf[4][2];
            int brow = lane & 7, bk = ((lane >> 3) & 1) * 16;
            #pragma unroll
            for (int n = 0; n < 4; n++) {
                uint32_t a = sb + CP_H + (uint32_t)(n0w + 8 * n + brow) * 144 + kt * 32 + bk;
                ldsm_x2(bhf[n], a);
                ldsm_x2(blf[n], a + (CP_L - CP_H));
            }
            #pragma unroll
            for (int mt = 0; mt < 4; mt++)
                #pragma unroll
                for (int n = 0; n < 4; n++) {
                    mma_bf16(acc1[mt][n], ah[mt], bhf[n]);
                    mma_bf16(acc1[mt][n], ah[mt], blf[n]);
                    mma_bf16(acc1[mt][n], al[mt], bhf[n]);
                }
        }
        // epilogue: exp -> kp bf16 hi/lo into CT (row n, col m pairs)
        float* dg = (float*)(smem + CD_);
        #pragma unroll
        for (int mt = 0; mt < 4; mt++)
            #pragma unroll
            for (int n = 0; n < 4; n++) {
                int r0 = 16 * mt + (lane >> 2);
                int col = n0w + 8 * n + 2 * (lane & 3);
                int gm = mhalf * 160 + col;
                float off0 = dg[r0] + gmax, off1 = dg[r0 + 8] + gmax;
                float k0 = (gm     < MFEAT) ? RATIO_C * __expf(acc1[mt][n][0] - off0) + REPS_C : 0.f;
                float k1 = (gm + 1 < MFEAT) ? RATIO_C * __expf(acc1[mt][n][1] - off0) + REPS_C : 0.f;
                float k2 = (gm     < MFEAT) ? RATIO_C * __expf(acc1[mt][n][2] - off1) + REPS_C : 0.f;
                float k3 = (gm + 1 < MFEAT) ? RATIO_C * __expf(acc1[mt][n][3] - off1) + REPS_C : 0.f;
                uint32_t hi, lo;
                split2(k0, k1, hi, lo);
                *(uint32_t*)(smem + CT_H + r0 * 336 + col * 2) = hi;
                *(uint32_t*)(smem + CT_L + r0 * 336 + col * 2) = lo;
                split2(k2, k3, hi, lo);
                *(uint32_t*)(smem + CT_H + (r0 + 8) * 336 + col * 2) = hi;
                *(uint32_t*)(smem + CT_L + (r0 + 8) * 336 + col * 2) = lo;
            }
        __syncthreads();

        // GEMM2: C[160 m x 72 e] += kp^T @ w  (trans ldmatrix, verified mapping)
        #pragma unroll
        for (int kk = 0; kk < 4; kk++) {
            uint32_t ath[2][4], atl[2][4];
            int kra = (lane & 7) + 8 * ((lane >> 4) & 1);
            int mhb = ((lane >> 3) & 1) * 16;
            #pragma unroll
            for (int t = 0; t < 2; t++) {
                uint32_t a = sb + CT_H + (uint32_t)(kk * 16 + kra) * 336 + 64 * w + 32 * t + mhb;
                ldsm_x4t(ath[t], a);
                ldsm_x4t(atl[t], a + (CT_L - CT_H));
            }
            uint32_t bwh[9][2], bwl[9][2];
            int krb = (lane & 7) + 8 * ((lane >> 3) & 1);
            #pragma unroll
            for (int n = 0; n < 9; n++) {
                uint32_t a = sb + CW_H + (uint32_t)(kk * 16 + krb) * 176 + 16 * n;
                ldsm_x2t(bwh[n], a);
                ldsm_x2t(bwl[n], a + (CW_L - CW_H));
            }
            #pragma unroll
            for (int t = 0; t < 2; t++)
                #pragma unroll
                for (int n = 0; n < 9; n++) {
                    mma_bf16(accC[t][n], ath[t], bwh[n]);
                    mma_bf16(accC[t][n], ath[t], bwl[n]);
                    mma_bf16(accC[t][n], atl[t], bwh[n]);
                }
        }
    }

    float* slab = g_ctxS + ((size_t)(ks * BH + bh)) * 72 * MP;
    #pragma unroll
    for (int t = 0; t < 2; t++)
        #pragma unroll
        for (int n = 0; n < 9; n++) {
            int mg = mhalf * 160 + 32 * w + 16 * t + (lane >> 2);
            int e = 8 * n + 2 * (lane & 3);
            slab[(size_t)e * MP + mg]           = accC[t][n][0];
            slab[(size_t)(e + 1) * MP + mg]     = accC[t][n][1];
            slab[(size_t)e * MP + mg + 8]       = accC[t][n][2];
            slab[(size_t)(e + 1) * MP + mg + 8] = accC[t][n][3];
        }
}

// ---------------------------------------------------------------------------
__global__ void convert_kernel() {
    int i = blockIdx.x * blockDim.x + threadIdx.x;
    int n = BH * 72 * 160;
    if (i >= n) return;
    int bh = i / (72 * 160), rem = i % (72 * 160);
    int e = rem / 160, p = rem % 160;
    float sx = 0.f, sy = 0.f;
    #pragma unroll
    for (int ks = 0; ks < KSPL; ks++) {
        float2 v = *(const float2*)(g_ctxS + (((size_t)(ks * BH + bh)) * 72 + e) * MP + 2 * p);
        sx += v.x; sy += v.y;
    }
    uint32_t hi, lo; split2(sx, sy, hi, lo);
    g_cthp[i] = hi; g_ctlp[i] = lo;
}

// ---------------------------------------------------------------------------
// out_fused: pass1 hi-only dd_q -> rowmax; pass2 3-term dd_q -> exp -> qp smem
// -> GEMM vs ctx^T chunks (ksum = col 64 -> denominator). No dd gmem.
// ---------------------------------------------------------------------------
#define OP_H 0
#define OP_L 46080
#define OQ_H 92160
#define OQ_L 110592
#define OS_H 129024
#define OS_L 147456
#define OC_H 165888
#define OC_L 176256
#define O_DG 186624
#define O_RA 187136
#define O_RB 187648
#define O_OFF 188160
#define OS2_SZ 188672

__global__ void __launch_bounds__(256) out_fused(const float* __restrict__ q_in,
                                                 const float* __restrict__ proj,
                                                 float* __restrict__ out) {
    extern __shared__ char smem[];
    uint32_t sb = smem_u32(smem);
    int tid = threadIdx.x, w = tid >> 5, lane = tid & 31;
    int bh = blockIdx.y, nt = blockIdx.x;
    const float* qb = q_in + ((size_t)bh * NSEQ + nt * 128) * DDIM;

    for (int i = tid; i < 128 * 32; i += 256) {
        int r = i >> 5, p = i & 31;
        float2 v = *(const float2*)(qb + r * 64 + 2 * p);
        uint32_t hi, lo; split2(DNORM * v.x, DNORM * v.y, hi, lo);
        *(uint32_t*)(smem + OQ_H + r * 144 + 4 * p) = hi;
        *(uint32_t*)(smem + OQ_L + r * 144 + 4 * p) = lo;
    }
    for (int i = tid; i < MP * 32; i += 256) {
        int r = i >> 5, p = i & 31;
        float2 v = (r < MFEAT) ? *(const float2*)(proj + r * 64 + 2 * p) : make_float2(0.f, 0.f);
        uint32_t hi, lo; split2(v.x, v.y, hi, lo);
        *(uint32_t*)(smem + OP_H + r * 144 + 4 * p) = hi;
        *(uint32_t*)(smem + OP_L + r * 144 + 4 * p) = lo;
    }
    if (tid < 128) {
        float s = 0.f;
        #pragma unroll
        for (int c = 0; c < DDIM; c++) { float x = qb[tid * 64 + c]; s += x * x; }
        ((float*)(smem + O_DG))[tid] = 0.0625f * s;
    }
    __syncthreads();

    int wr = w & 3, wc = w >> 2, m0 = 32 * wr;

    // pass 1: hi-only rowmax
    float rm[4] = {NEGINF, NEGINF, NEGINF, NEGINF};
    #pragma unroll 1
    for (int ch = 0; ch < 5; ch++) {
        float a1[2][4][4];
        #pragma unroll
        for (int mt = 0; mt < 2; mt++)
            #pragma unroll
            for (int n = 0; n < 4; n++)
                #pragma unroll
                for (int x = 0; x < 4; x++) a1[mt][n][x] = 0.f;
        #pragma unroll
        for (int kt = 0; kt < 4; kt++) {
            uint32_t ah[2][4];
            int arow = lane & 15, koff = (lane >> 4) * 16;
            #pragma unroll
            for (int mt = 0; mt < 2; mt++)
                ldsm_x4(ah[mt], sb + OQ_H + (uint32_t)(m0 + 16 * mt + arow) * 144 + kt * 32 + koff);
            uint32_t bf[4][2];
            int brow = lane & 7, bk = ((lane >> 3) & 1) * 16;
            #pragma unroll
            for (int n = 0; n < 4; n++)
                ldsm_x2(bf[n], sb + OP_H + (uint32_t)(ch * 64 + 32 * wc + 8 * n + brow) * 144 + kt * 32 + bk);
            #pragma unroll
            for (int mt = 0; mt < 2; mt++)
                #pragma unroll
                for (int n = 0; n < 4; n++) mma_bf16(a1[mt][n], ah[mt], bf[n]);
        }
        #pragma unroll
        for (int mt = 0; mt < 2; mt++)
            #pragma unroll
            for (int n = 0; n < 4; n++) {
                int gm = ch * 64 + 32 * wc + 8 * n + 2 * (lane & 3);
                bool v0 = gm < MFEAT, v1 = gm + 1 < MFEAT;
                rm[2 * mt]     = fmaxf(rm[2 * mt],     fmaxf(v0 ? a1[mt][n][0] : NEGINF, v1 ? a1[mt][n][1] : NEGINF));
                rm[2 * mt + 1] = fmaxf(rm[2 * mt + 1], fmaxf(v0 ? a1[mt][n][2] : NEGINF, v1 ? a1[mt][n][3] : NEGINF));
            }
    }
    #pragma unroll
    for (int i = 0; i < 4; i++) {
        rm[i] = fmaxf(rm[i], __shfl_xor_sync(0xffffffffu, rm[i], 1));
        rm[i] = fmaxf(rm[i], __shfl_xor_sync(0xffffffffu, rm[i], 2));
    }
    if ((lane & 3) == 0) {
        float* rb = (float*)(smem + (wc ? O_RB : O_RA));
        rb[m0 + (lane >> 2)]      = rm[0];
        rb[m0 + 8 + (lane >> 2)]  = rm[1];
        rb[m0 + 16 + (lane >> 2)] = rm[2];
        rb[m0 + 24 + (lane >> 2)] = rm[3];
    }
    __syncthreads();
    if (tid < 128)
        ((float*)(smem + O_OFF))[tid] = ((float*)(smem + O_DG))[tid] +
            fmaxf(((float*)(smem + O_RA))[tid], ((float*)(smem + O_RB))[tid]);
    __syncthreads();

    // pass 2: recompute dd (3-term), exp -> qp smem, GEMM2 vs ctx chunks
    float accO[9][4];
    #pragma unroll
    for (int n = 0; n < 9; n++)
        #pragma unroll
        for (int x = 0; x < 4; x++) accO[n][x] = 0.f;

    #pragma unroll 1
    for (int ch = 0; ch < 5; ch++) {
        float a1[2][4][4];
        #pragma unroll
        for (int mt = 0; mt < 2; mt++)
            #pragma unroll
            for (int n = 0; n < 4; n++)
                #pragma unroll
                for (int x = 0; x < 4; x++) a1[mt][n][x] = 0.f;
        #pragma unroll
        for (int kt = 0; kt < 4; kt++) {
            uint32_t ah[2][4], al[2][4];
            int arow = lane & 15, koff = (lane >> 4) * 16;
            #pragma unroll
            for (int mt = 0; mt < 2; mt++) {
                uint32_t a = sb + OQ_H + (uint32_t)(m0 + 16 * mt + arow) * 144 + kt * 32 + koff;
                ldsm_x4(ah[mt], a);
                ldsm_x4(al[mt], a + (OQ_L - OQ_H));
            }
            uint32_t bhf[4][2], blf[4][2];
            int brow = lane & 7, bk = ((lane >> 3) & 1) * 16;
            #pragma unroll
            for (int n = 0; n < 4; n++) {
                uint32_t a = sb + OP_H + (uint32_t)(ch * 64 + 32 * wc + 8 * n + brow) * 144 + kt * 32 + bk;
                ldsm_x2(bhf[n], a);
                ldsm_x2(blf[n], a + (OP_L - OP_H));
            }
            #pragma unroll
            for (int mt = 0; mt < 2; mt++)
                #pragma unroll
                for (int n = 0; n < 4; n++) {
                    mma_bf16(a1[mt][n], ah[mt], bhf[n]);
                    mma_bf16(a1[mt][n], ah[mt], blf[n]);
                    mma_bf16(a1[mt][n], al[mt], bhf[n]);
                }
        }
        float* offp = (float*)(smem + O_OFF);
        #pragma unroll
        for (int mt = 0; mt < 2; mt++)
            #pragma unroll
            for (int n = 0; n < 4; n++) {
                int r0 = m0 + 16 * mt + (lane >> 2);
                int col = 32 * wc + 8 * n + 2 * (lane & 3);
                int gm = ch * 64 + col;
                float off0 = offp[r0], off1 = offp[r0 + 8];
                float q0 = (gm     < MFEAT) ? RATIO_C * __expf(a1[mt][n][0] - off0) + REPS_C : 0.f;
                float q1 = (gm + 1 < MFEAT) ? RATIO_C * __expf(a1[mt][n][1] - off0) + REPS_C : 0.f;
                float q2 = (gm     < MFEAT) ? RATIO_C * __expf(a1[mt][n][2] - off1) + REPS_C : 0.f;
                float q3 = (gm + 1 < MFEAT) ? RATIO_C * __expf(a1[mt][n][3] - off1) + REPS_C : 0.f;
                uint32_t hi, lo;
                split2(q0, q1, hi, lo);
                *(uint32_t*)(smem + OS_H + r0 * 144 + col * 2) = hi;
                *(uint32_t*)(smem + OS_L + r0 * 144 + col * 2) = lo;
                split2(q2, q3, hi, lo);
                *(uint32_t*)(smem + OS_H + (r0 + 8) * 144 + col * 2) = hi;
                *(uint32_t*)(smem + OS_L + (r0 + 8) * 144 + col * 2) = lo;
            }
        // stage ctx chunk [72 e x 32 m-pairs]
        for (int i = tid; i < 72 * 32; i += 256) {
            int e = i >> 5, p = i & 31;
            *(uint32_t*)(smem + OC_H + e * 144 + 4 * p) = g_cthp[(bh * 72 + e) * 160 + 32 * ch + p];
            *(uint32_t*)(smem + OC_L + e * 144 + 4 * p) = g_ctlp[(bh * 72 + e) * 160 + 32 * ch + p];
        }
        __syncthreads();

        int row = 16 * w + (lane & 15), koff2 = (lane >> 4) * 16;
        #pragma unroll
        for (int kt = 0; kt < 4; kt++) {
            uint32_t ah2[4], al2[4];
            uint32_t a = sb + OS_H + (uint32_t)row * 144 + kt * 32 + koff2;
            ldsm_x4(ah2, a);
            ldsm_x4(al2, a + (OS_L - OS_H));
            uint32_t bhf[9][2], blf[9][2];
            int brow = lane & 7, bk = ((lane >> 3) & 1) * 16;
            #pragma unroll
            for (int n = 0; n < 9; n++) {
                uint32_t b = sb + OC_H + (uint32_t)(8 * n + brow) * 144 + kt * 32 + bk;
                ldsm_x2(bhf[n], b);
                ldsm_x2(blf[n], b + (OC_L - OC_H));
            }
            #pragma unroll
            for (int n = 0; n < 9; n++) {
                mma_bf16(accO[n], ah2, bhf[n]);
                mma_bf16(accO[n], ah2, blf[n]);
                mma_bf16(accO[n], al2, bhf[n]);
            }
        }
        __syncthreads();
    }

    float d0 = __shfl_sync(0xffffffffu, accO[8][0], lane & ~3);
    float d1 = __shfl_sync(0xffffffffu, accO[8][2], lane & ~3);
    float i0 = 1.0f / d0, i1 = 1.0f / d1;
    int r0 = nt * 128 + 16 * w + (lane >> 2);
    float* ob = out + (size_t)bh * NSEQ * DDIM;
    #pragma unroll
    for (int n = 0; n < 8; n++) {
        int col = 8 * n + 2 * (lane & 3);
        *(float2*)(ob + (size_t)r0 * DDIM + col) = make_float2(i0 * accO[n][0], i0 * accO[n][1]);
        *(float2*)(ob + (size_t)(r0 + 8) * DDIM + col) = make_float2(i1 * accO[n][2], i1 * accO[n][3]);
    }
}

// ---------------------------------------------------------------------------
extern "C" void kernel_launch(void* const* d_in, const int* in_sizes, int n_in,
                              void* d_out, int out_size) {
    const float* q    = (const float*)d_in[0];
    const float* k    = (const float*)d_in[1];
    const float* v    = (const float*)d_in[2];
    const float* proj = (const float*)d_in[3];
    float* out = (float*)d_out;

    cudaFuncSetAttribute(kmax_kernel, cudaFuncAttributeMaxDynamicSharedMemorySize, KM_SZ);
    cudaFuncSetAttribute(ctx_fused,   cudaFuncAttributeMaxDynamicSharedMemorySize, CX_SZ);
    cudaFuncSetAttribute(out_fused,   cudaFuncAttributeMaxDynamicSharedMemorySize, OS2_SZ);

    init_kernel<<<1, 32>>>();
    kmax_kernel<<<dim3(NT, BH), 256, KM_SZ>>>(k, proj);
    ctx_fused<<<dim3(2 * KSPL, BH), 160, CX_SZ>>>(k, v, proj);
    convert_kernel<<<(BH * 72 * 160 + 255) / 256, 256>>>();
    out_fused<<<dim3(NT, BH), 256, OS2_SZ>>>(q, proj, out);
}